// round 8
// baseline (speedup 1.0000x reference)
#include <cuda_runtime.h>
#include <cstddef>
#include <cstdint>

#define D_MODEL   1024
#define NUM_HEADS 16
#define DEPTH     64
#define BATCH     2
#define SEQ       2048
#define M_ROWS    (BATCH * SEQ)   // 4096

// ---------------------------------------------------------------------------
// Scratch
// ---------------------------------------------------------------------------
__device__ float g_qh[BATCH * NUM_HEADS * SEQ * DEPTH];   // [B,H,S,64]
__device__ float g_kh[BATCH * NUM_HEADS * SEQ * DEPTH];
__device__ float g_vh[BATCH * NUM_HEADS * SEQ * DEPTH];
__device__ float g_att[BATCH * SEQ * D_MODEL];            // [B,S,H*64]

// ---------------------------------------------------------------------------
// Helpers
// ---------------------------------------------------------------------------
__device__ __forceinline__ unsigned f2tf(float f) {
    unsigned u;
    asm("cvt.rna.tf32.f32 %0, %1;" : "=r"(u) : "f"(f));
    return u;
}

__device__ __forceinline__ uint32_t smem_u32(const void* p) {
    uint32_t a;
    asm("{ .reg .u64 t; cvta.to.shared.u64 t, %1; cvt.u32.u64 %0, t; }" : "=r"(a) : "l"(p));
    return a;
}

__device__ __forceinline__ void mma8(float* c, const unsigned* a, const unsigned* b) {
    asm volatile(
        "mma.sync.aligned.m16n8k8.row.col.f32.tf32.tf32.f32 "
        "{%0,%1,%2,%3},{%4,%5,%6,%7},{%8,%9},{%0,%1,%2,%3};"
        : "+f"(c[0]), "+f"(c[1]), "+f"(c[2]), "+f"(c[3])
        : "r"(a[0]), "r"(a[1]), "r"(a[2]), "r"(a[3]), "r"(b[0]), "r"(b[1]));
}

__device__ __forceinline__ void ldm_x4(unsigned* d, uint32_t addr) {
    asm volatile("ldmatrix.sync.aligned.m8n8.x4.shared.b16 {%0,%1,%2,%3}, [%4];"
                 : "=r"(d[0]), "=r"(d[1]), "=r"(d[2]), "=r"(d[3]) : "r"(addr));
}

// ---------------------------------------------------------------------------
// tf32 GEMM: block 128x128, BK=16, 4 warps (2x2), warp tile 64x64.
// Smem rows = 64B (16 floats of K), swizzle chunk c ^= (row>>1)&3.
// ---------------------------------------------------------------------------
#define BK 16

__device__ __forceinline__ void gemm_mma_core(
    const float* __restrict__ A, const float* __restrict__ W,
    const float* __restrict__ bias, float* __restrict__ C,
    int head_split, int m0, int n0)
{
    __shared__ __align__(16) unsigned As[2][128 * BK];
    __shared__ __align__(16) unsigned Bs[2][128 * BK];

    const int tid  = threadIdx.x;     // 0..127
    const int lane = tid & 31;
    const int w    = tid >> 5;        // 0..3
    const int wm   = w >> 1;          // 0..1
    const int wn   = w & 1;           // 0..1

    const uint32_t asb = smem_u32(&As[0][0]);
    const uint32_t bsb = smem_u32(&Bs[0][0]);

    float acc[4][8][4];
#pragma unroll
    for (int i = 0; i < 4; i++)
#pragma unroll
        for (int j = 0; j < 8; j++)
#pragma unroll
            for (int e = 0; e < 4; e++) acc[i][j][e] = 0.f;

    // staging: thread t stages full BK-row t of A and of B (4 chunks of 16B each)
    const float* Ap = A + (size_t)(m0 + tid) * D_MODEL;
    const float* Wp = W + (size_t)(n0 + tid) * D_MODEL;
    const int swb = (tid >> 1) & 3;
    // swizzled chunk offsets in unsigned units
    int sto[4];
#pragma unroll
    for (int c = 0; c < 4; c++) sto[c] = tid * 16 + ((c ^ swb) << 2);

    float4 pa[4], pb[4];
#pragma unroll
    for (int c = 0; c < 4; c++) {
        pa[c] = *(const float4*)(Ap + c * 4);
        pb[c] = *(const float4*)(Wp + c * 4);
    }

    // ldmatrix lane addresses (byte offsets within one buffer)
    uint32_t a_off[4][2], b_off[4][2];
#pragma unroll
    for (int i = 0; i < 4; i++) {
        const int r = wm * 64 + i * 16 + (lane & 7) + ((lane >> 3) & 1) * 8;
#pragma unroll
        for (int kt = 0; kt < 2; kt++) {
            const int c = 2 * kt + (lane >> 4);
            a_off[i][kt] = r * 64 + ((c ^ ((r >> 1) & 3)) << 4);
        }
    }
#pragma unroll
    for (int jp = 0; jp < 4; jp++) {
        const int r = wn * 64 + (2 * jp + (lane >> 4)) * 8 + (lane & 7);
#pragma unroll
        for (int kt = 0; kt < 2; kt++) {
            const int c = 2 * kt + ((lane >> 3) & 1);
            b_off[jp][kt] = r * 64 + ((c ^ ((r >> 1) & 3)) << 4);
        }
    }

    const int NSTEPS = D_MODEL / BK;   // 64
#pragma unroll 1
    for (int s = 0; s < NSTEPS; s++) {
        const int buf  = s & 1;
        const int bofU = buf * 128 * BK;
        // ---- stage prefetched regs -> smem[buf] ----
#pragma unroll
        for (int c = 0; c < 4; c++) {
            uint4 u;
            u.x = f2tf(pa[c].x); u.y = f2tf(pa[c].y); u.z = f2tf(pa[c].z); u.w = f2tf(pa[c].w);
            *(uint4*)(&As[0][0] + bofU + sto[c]) = u;
            u.x = f2tf(pb[c].x); u.y = f2tf(pb[c].y); u.z = f2tf(pb[c].z); u.w = f2tf(pb[c].w);
            *(uint4*)(&Bs[0][0] + bofU + sto[c]) = u;
        }
        __syncthreads();

        // ---- prefetch next K-slab ----
        if (s + 1 < NSTEPS) {
            const int k0 = (s + 1) * BK;
#pragma unroll
            for (int c = 0; c < 4; c++) {
                pa[c] = *(const float4*)(Ap + k0 + c * 4);
                pb[c] = *(const float4*)(Wp + k0 + c * 4);
            }
        }

        // ---- compute on smem[buf] ----
        const uint32_t abase = asb + buf * (128 * BK * 4);
        const uint32_t bbase = bsb + buf * (128 * BK * 4);
#pragma unroll
        for (int kt = 0; kt < 2; kt++) {
            unsigned bf[8][2];
#pragma unroll
            for (int jp = 0; jp < 4; jp++) {
                unsigned t4[4];
                ldm_x4(t4, bbase + b_off[jp][kt]);
                bf[2 * jp][0]     = t4[0]; bf[2 * jp][1]     = t4[1];
                bf[2 * jp + 1][0] = t4[2]; bf[2 * jp + 1][1] = t4[3];
            }
#pragma unroll
            for (int i = 0; i < 4; i++) {
                unsigned af[4];
                ldm_x4(af, abase + a_off[i][kt]);
#pragma unroll
                for (int j = 0; j < 8; j++) mma8(acc[i][j], af, bf[j]);
            }
        }
        // single sync per step: next iter writes the other buffer.
    }

    // ---- epilogue ----
#pragma unroll
    for (int i = 0; i < 4; i++) {
#pragma unroll
        for (int j = 0; j < 8; j++) {
            const int m = m0 + wm * 64 + i * 16 + (lane >> 2);
            const int n = n0 + wn * 64 + j * 8 + 2 * (lane & 3);
            const float2 bb = *(const float2*)(bias + n);
            float2 v0, v1;
            v0.x = acc[i][j][0] + bb.x; v0.y = acc[i][j][1] + bb.y;
            v1.x = acc[i][j][2] + bb.x; v1.y = acc[i][j][3] + bb.y;
            if (head_split) {
                const int h = n >> 6, d = n & 63;
                const int b0r = m >> 11, s0r = m & (SEQ - 1);
                const int b1r = (m + 8) >> 11, s1r = (m + 8) & (SEQ - 1);
                *(float2*)&C[(((size_t)b0r * NUM_HEADS + h) * SEQ + s0r) * DEPTH + d] = v0;
                *(float2*)&C[(((size_t)b1r * NUM_HEADS + h) * SEQ + s1r) * DEPTH + d] = v1;
            } else {
                *(float2*)&C[(size_t)m * D_MODEL + n] = v0;
                *(float2*)&C[(size_t)(m + 8) * D_MODEL + n] = v1;
            }
        }
    }
}

__global__ __launch_bounds__(128, 2) void gemm_qkv(
    const float* __restrict__ q, const float* __restrict__ k, const float* __restrict__ v,
    const float* __restrict__ wq, const float* __restrict__ bq,
    const float* __restrict__ wk, const float* __restrict__ bk,
    const float* __restrict__ wv, const float* __restrict__ bv,
    float* __restrict__ qh, float* __restrict__ kh, float* __restrict__ vh)
{
    const int z = blockIdx.z;
    const float* A = (z == 0) ? q : (z == 1) ? k : v;
    const float* W = (z == 0) ? wq : (z == 1) ? wk : wv;
    const float* B = (z == 0) ? bq : (z == 1) ? bk : bv;
    float*       C = (z == 0) ? qh : (z == 1) ? kh : vh;
    gemm_mma_core(A, W, B, C, 1, blockIdx.y * 128, blockIdx.x * 128);
}

__global__ __launch_bounds__(128, 2) void gemm_dense(
    const float* __restrict__ A, const float* __restrict__ W,
    const float* __restrict__ bias, float* __restrict__ C)
{
    gemm_mma_core(A, W, bias, C, 0, blockIdx.y * 128, blockIdx.x * 128);
}

// ---------------------------------------------------------------------------
// FA2-style causal attention, tf32 mma.
// 256 thr (8 warps), 128 q/block, 64-key tiles, paired q-tiles (bx, 15-bx).
// NEW: double-buffered K/V (smem: Kf/Vf x2 = 64KB), single sync per tile,
//      shuffle-based P C-frag -> A-frag conversion (no P smem round-trip).
// ash layout (unsigned units): buf*8192 + [0..4095]=Kf, [4096..8191]=Vf
// ---------------------------------------------------------------------------
#define ATTN_THREADS 256
#define ATTN_SMEM_BYTES 65536

__device__ __forceinline__ void attn_stage(
    unsigned* __restrict__ ash, int base,
    const float* __restrict__ kb, const float* __restrict__ vb,
    int t, int tid)
{
    // K: fragment layout for QK^T B-operand
    for (int c = tid; c < 512; c += ATTN_THREADS) {
        const int key = c >> 3;
        const int kt  = c & 7;
        const float* src = kb + (size_t)(t * 64 + key) * DEPTH + kt * 8;
        const float4 a0 = *(const float4*)(src);
        const float4 a1 = *(const float4*)(src + 4);
        unsigned* dst = ash + base + ((kt * 8 + (key >> 3)) * 32 + (key & 7) * 4) * 2;
        uint4 s0, s1;
        s0.x = f2tf(a0.x); s0.y = f2tf(a1.x); s0.z = f2tf(a0.y); s0.w = f2tf(a1.y);
        s1.x = f2tf(a0.z); s1.y = f2tf(a1.z); s1.z = f2tf(a0.w); s1.w = f2tf(a1.w);
        ((uint4*)dst)[0] = s0;
        ((uint4*)dst)[1] = s1;
    }
    // V: fragment layout for PV B-operand
    for (int u = tid; u < 512; u += ATTN_THREADS) {
        const int kg = u >> 6;
        const int kl = (u >> 4) & 3;
        const int dc = u & 15;
        const int keyA = kg * 8 + kl;
        const float4 va = *(const float4*)(vb + (size_t)(t * 64 + keyA)     * DEPTH + dc * 4);
        const float4 vB = *(const float4*)(vb + (size_t)(t * 64 + keyA + 4) * DEPTH + dc * 4);
        unsigned* dst = ash + base + 4096 + ((kg * 8 + (dc >> 1)) * 32 + (dc & 1) * 16 + kl) * 2;
        uint2 p0; p0.x = f2tf(va.x); p0.y = f2tf(vB.x); *(uint2*)(dst + 0)  = p0;
        uint2 p1; p1.x = f2tf(va.y); p1.y = f2tf(vB.y); *(uint2*)(dst + 8)  = p1;
        uint2 p2; p2.x = f2tf(va.z); p2.y = f2tf(vB.z); *(uint2*)(dst + 16) = p2;
        uint2 p3; p3.x = f2tf(va.w); p3.y = f2tf(vB.w); *(uint2*)(dst + 24) = p3;
    }
}

__global__ __launch_bounds__(ATTN_THREADS, 2) void attn_tf32(
    const float* __restrict__ Qg, const float* __restrict__ Kg,
    const float* __restrict__ Vg, float* __restrict__ Og)
{
    extern __shared__ unsigned ash[];

    const int tid  = threadIdx.x;
    const int lane = tid & 31;
    const int w    = tid >> 5;
    const int b    = blockIdx.z;
    const int h    = blockIdx.y;

    const size_t hoff = ((size_t)(b * NUM_HEADS + h) * SEQ) * DEPTH;
    const float* kb = Kg + hoff;
    const float* vb = Vg + hoff;

    const int r0 = lane >> 2;
    const int c0 = lane & 3;
    // shuffle-P source lanes
    const int lo = (lane & 28) | ((lane & 3) >> 1);
    const int hi = lo + 2;
    const bool oddc = (lane & 1);

#pragma unroll 1
    for (int pass = 0; pass < 2; pass++) {
        const int p  = pass ? (15 - (int)blockIdx.x) : (int)blockIdx.x;
        const int q0 = p * 128;

        unsigned qa[8][4];
        {
            const float* qbase = Qg + hoff + (size_t)(q0 + w * 16) * DEPTH;
#pragma unroll
            for (int kt = 0; kt < 8; kt++) {
                qa[kt][0] = f2tf(qbase[(size_t)(r0)     * DEPTH + kt * 8 + c0]);
                qa[kt][1] = f2tf(qbase[(size_t)(r0 + 8) * DEPTH + kt * 8 + c0]);
                qa[kt][2] = f2tf(qbase[(size_t)(r0)     * DEPTH + kt * 8 + c0 + 4]);
                qa[kt][3] = f2tf(qbase[(size_t)(r0 + 8) * DEPTH + kt * 8 + c0 + 4]);
            }
        }

        float o[8][4];
#pragma unroll
        for (int j = 0; j < 8; j++)
#pragma unroll
            for (int e = 0; e < 4; e++) o[j][e] = 0.f;
        float m0r = -1e30f, m1r = -1e30f;
        float l0r = 0.f,    l1r = 0.f;

        const int ntile = 2 * p + 2;
        const int qhiW  = q0 + w * 16 + 15;
        const int qrow  = q0 + w * 16 + r0;

        // stage tile 0 into buffer 0
        attn_stage(ash, 0, kb, vb, 0, tid);

#pragma unroll 1
        for (int t = 0; t < ntile; t++) {
            __syncthreads();                     // tile t staged by all warps
            const int base = (t & 1) * 8192;
            const bool active = (t * 64 <= qhiW);

            float s[8][4];
            if (active) {
                // ---- S = Q @ K^T ----
#pragma unroll
                for (int j = 0; j < 8; j++) {
#pragma unroll
                    for (int e = 0; e < 4; e++) s[j][e] = 0.f;
#pragma unroll
                    for (int kt = 0; kt < 8; kt++) {
                        const uint2 b2 = ((const uint2*)(ash + base + (kt * 8 + j) * 64))[lane];
                        unsigned bf[2] = {b2.x, b2.y};
                        mma8(s[j], qa[kt], bf);
                    }
                }

                // ---- scale + causal mask + online softmax ----
                const bool diag = (t >= ntile - 2);
                float mx0 = -1e30f, mx1 = -1e30f;
#pragma unroll
                for (int j = 0; j < 8; j++) {
#pragma unroll
                    for (int e = 0; e < 4; e++) {
                        float vv = s[j][e] * 0.125f;
                        if (diag) {
                            const int key = t * 64 + j * 8 + 2 * (lane & 3) + (e & 1);
                            const int qq  = qrow + ((e >> 1) << 3);
                            if (key > qq) vv = -1e30f;
                        }
                        s[j][e] = vv;
                    }
                    mx0 = fmaxf(mx0, fmaxf(s[j][0], s[j][1]));
                    mx1 = fmaxf(mx1, fmaxf(s[j][2], s[j][3]));
                }
                mx0 = fmaxf(mx0, __shfl_xor_sync(0xffffffffu, mx0, 1));
                mx0 = fmaxf(mx0, __shfl_xor_sync(0xffffffffu, mx0, 2));
                mx1 = fmaxf(mx1, __shfl_xor_sync(0xffffffffu, mx1, 1));
                mx1 = fmaxf(mx1, __shfl_xor_sync(0xffffffffu, mx1, 2));

                const float mn0 = fmaxf(m0r, mx0);
                const float mn1 = fmaxf(m1r, mx1);
                const float al0 = __expf(m0r - mn0);
                const float al1 = __expf(m1r - mn1);

                float ls0 = 0.f, ls1 = 0.f;
#pragma unroll
                for (int j = 0; j < 8; j++) {
                    s[j][0] = __expf(s[j][0] - mn0); ls0 += s[j][0];
                    s[j][1] = __expf(s[j][1] - mn0); ls0 += s[j][1];
                    s[j][2] = __expf(s[j][2] - mn1); ls1 += s[j][2];
                    s[j][3] = __expf(s[j][3] - mn1); ls1 += s[j][3];
                }
                ls0 += __shfl_xor_sync(0xffffffffu, ls0, 1);
                ls0 += __shfl_xor_sync(0xffffffffu, ls0, 2);
                ls1 += __shfl_xor_sync(0xffffffffu, ls1, 1);
                ls1 += __shfl_xor_sync(0xffffffffu, ls1, 2);

                l0r = l0r * al0 + ls0;
                l1r = l1r * al1 + ls1;
                m0r = mn0; m1r = mn1;

#pragma unroll
                for (int j = 0; j < 8; j++) {
                    o[j][0] *= al0; o[j][1] *= al0;
                    o[j][2] *= al1; o[j][3] *= al1;
                }
            }

            // ---- stage tile t+1 into other buffer (overlaps PV below) ----
            if (t + 1 < ntile)
                attn_stage(ash, ((t + 1) & 1) * 8192, kb, vb, t + 1, tid);

            if (active) {
                // ---- P C-frag -> A-frag via shuffles, then O += P @ V ----
#pragma unroll
                for (int kt = 0; kt < 8; kt++) {
                    const unsigned p0 = f2tf(s[kt][0]);
                    const unsigned p1 = f2tf(s[kt][1]);
                    const unsigned p2 = f2tf(s[kt][2]);
                    const unsigned p3 = f2tf(s[kt][3]);
                    unsigned af[4], u0, u1;
                    u0 = __shfl_sync(0xffffffffu, p0, lo);
                    u1 = __shfl_sync(0xffffffffu, p1, lo);
                    af[0] = oddc ? u1 : u0;
                    u0 = __shfl_sync(0xffffffffu, p2, lo);
                    u1 = __shfl_sync(0xffffffffu, p3, lo);
                    af[1] = oddc ? u1 : u0;
                    u0 = __shfl_sync(0xffffffffu, p0, hi);
                    u1 = __shfl_sync(0xffffffffu, p1, hi);
                    af[2] = oddc ? u1 : u0;
                    u0 = __shfl_sync(0xffffffffu, p2, hi);
                    u1 = __shfl_sync(0xffffffffu, p3, hi);
                    af[3] = oddc ? u1 : u0;
#pragma unroll
                    for (int j = 0; j < 8; j++) {
                        const uint2 b2 = ((const uint2*)(ash + base + 4096 + (kt * 8 + j) * 64))[lane];
                        unsigned bf[2] = {b2.x, b2.y};
                        mma8(o[j], af, bf);
                    }
                }
            }
        }

        // ---- epilogue ----
        const float inv0 = 1.f / l0r;
        const float inv1 = 1.f / l1r;
        const int qq = q0 + w * 16 + r0;
#pragma unroll
        for (int j = 0; j < 8; j++) {
            const int col = j * 8 + 2 * (lane & 3);
            float2 v0, v1;
            v0.x = o[j][0] * inv0; v0.y = o[j][1] * inv0;
            v1.x = o[j][2] * inv1; v1.y = o[j][3] * inv1;
            *(float2*)&Og[((size_t)(b * SEQ + qq))     * D_MODEL + h * DEPTH + col] = v0;
            *(float2*)&Og[((size_t)(b * SEQ + qq + 8)) * D_MODEL + h * DEPTH + col] = v1;
        }
        __syncthreads();   // pass boundary: buffers reused from t=0 next pass
    }
}

// ---------------------------------------------------------------------------
// Launch
// ---------------------------------------------------------------------------
extern "C" void kernel_launch(void* const* d_in, const int* in_sizes, int n_in,
                              void* d_out, int out_size)
{
    const float* v       = (const float*)d_in[0];
    const float* k       = (const float*)d_in[1];
    const float* q       = (const float*)d_in[2];
    // d_in[3] = mask (causal triu) -- analytic in attn kernel
    const float* wq_w    = (const float*)d_in[4];
    const float* wq_b    = (const float*)d_in[5];
    const float* wk_w    = (const float*)d_in[6];
    const float* wk_b    = (const float*)d_in[7];
    const float* wv_w    = (const float*)d_in[8];
    const float* wv_b    = (const float*)d_in[9];
    const float* dense_w = (const float*)d_in[10];
    const float* dense_b = (const float*)d_in[11];
    float* out = (float*)d_out;

    float *qh, *kh, *vh, *att;
    cudaGetSymbolAddress((void**)&qh,  g_qh);
    cudaGetSymbolAddress((void**)&kh,  g_kh);
    cudaGetSymbolAddress((void**)&vh,  g_vh);
    cudaGetSymbolAddress((void**)&att, g_att);

    cudaFuncSetAttribute(attn_tf32,
                         cudaFuncAttributeMaxDynamicSharedMemorySize, ATTN_SMEM_BYTES);

    const dim3 pgrid(D_MODEL / 128, M_ROWS / 128, 3);   // (8, 32, 3)
    gemm_qkv<<<pgrid, 128>>>(q, k, v, wq_w, wq_b, wk_w, wk_b, wv_w, wv_b,
                             qh, kh, vh);

    const dim3 agrid(SEQ / 256, NUM_HEADS, BATCH);      // (8, 16, 2) paired tiles
    attn_tf32<<<agrid, ATTN_THREADS, ATTN_SMEM_BYTES>>>(qh, kh, vh, att);

    const dim3 dgrid(D_MODEL / 128, M_ROWS / 128);      // (8, 32)
    gemm_dense<<<dgrid, 128>>>(att, dense_w, dense_b, out);
}

// round 10
// speedup vs baseline: 2.1727x; 2.1727x over previous
#include <cuda_runtime.h>
#include <cuda_fp16.h>
#include <cstddef>
#include <cstdint>

#define D_MODEL   1024
#define NUM_HEADS 16
#define DEPTH     64
#define BATCH     2
#define SEQ       2048
#define M_ROWS    (BATCH * SEQ)   // 4096

// ---------------------------------------------------------------------------
// Scratch (all fp16 intermediates; f32 only for biases & final output)
// ---------------------------------------------------------------------------
__device__ __half g_qf[M_ROWS * D_MODEL];    // converted inputs
__device__ __half g_kf[M_ROWS * D_MODEL];
__device__ __half g_vf[M_ROWS * D_MODEL];
__device__ __half g_wq[D_MODEL * D_MODEL];   // converted weights
__device__ __half g_wk[D_MODEL * D_MODEL];
__device__ __half g_wv[D_MODEL * D_MODEL];
__device__ __half g_wd[D_MODEL * D_MODEL];
__device__ __half g_qh[BATCH * NUM_HEADS * SEQ * DEPTH];   // projections [B,H,S,64]
__device__ __half g_kh[BATCH * NUM_HEADS * SEQ * DEPTH];
__device__ __half g_vh[BATCH * NUM_HEADS * SEQ * DEPTH];
__device__ __half g_att[M_ROWS * D_MODEL];   // attention out, concat layout

// ---------------------------------------------------------------------------
// Helpers
// ---------------------------------------------------------------------------
__device__ __forceinline__ uint32_t smem_u32(const void* p) {
    uint32_t a;
    asm("{ .reg .u64 t; cvta.to.shared.u64 t, %1; cvt.u32.u64 %0, t; }" : "=r"(a) : "l"(p));
    return a;
}

__device__ __forceinline__ unsigned pack2(float a, float b) {
    __half2 h = __floats2half2_rn(a, b);   // low half = a
    return *reinterpret_cast<unsigned*>(&h);
}

__device__ __forceinline__ void mma16(float* c, const unsigned* a, const unsigned* b) {
    asm volatile(
        "mma.sync.aligned.m16n8k16.row.col.f32.f16.f16.f32 "
        "{%0,%1,%2,%3},{%4,%5,%6,%7},{%8,%9},{%0,%1,%2,%3};"
        : "+f"(c[0]), "+f"(c[1]), "+f"(c[2]), "+f"(c[3])
        : "r"(a[0]), "r"(a[1]), "r"(a[2]), "r"(a[3]), "r"(b[0]), "r"(b[1]));
}

__device__ __forceinline__ void ldm_x4(unsigned* d, uint32_t addr) {
    asm volatile("ldmatrix.sync.aligned.m8n8.x4.shared.b16 {%0,%1,%2,%3}, [%4];"
                 : "=r"(d[0]), "=r"(d[1]), "=r"(d[2]), "=r"(d[3]) : "r"(addr));
}
__device__ __forceinline__ void ldm_x4_t(unsigned* d, uint32_t addr) {
    asm volatile("ldmatrix.sync.aligned.m8n8.x4.trans.shared.b16 {%0,%1,%2,%3}, [%4];"
                 : "=r"(d[0]), "=r"(d[1]), "=r"(d[2]), "=r"(d[3]) : "r"(addr));
}

#define CP16(dst, src) \
    asm volatile("cp.async.cg.shared.global [%0], [%1], 16;" :: "r"(dst), "l"(src) : "memory")
#define CP_COMMIT() asm volatile("cp.async.commit_group;" ::: "memory")
#define CP_WAIT(n)  asm volatile("cp.async.wait_group %0;" :: "n"(n) : "memory")

// ---------------------------------------------------------------------------
// Conversion kernels (f32 -> f16), vectorized
// ---------------------------------------------------------------------------
__global__ void cvt_qkv(const float* __restrict__ q, const float* __restrict__ k,
                        const float* __restrict__ v,
                        __half* dq, __half* dk, __half* dv)
{
    const int z = blockIdx.z;
    const float* s = (z == 0) ? q : (z == 1) ? k : v;
    __half* d      = (z == 0) ? dq : (z == 1) ? dk : dv;
    const int i = blockIdx.x * blockDim.x + threadIdx.x;   // per float4
    const float4 f = ((const float4*)s)[i];
    uint2 u;
    u.x = pack2(f.x, f.y);
    u.y = pack2(f.z, f.w);
    ((uint2*)d)[i] = u;
}

__global__ void cvt_w(const float* __restrict__ w0, const float* __restrict__ w1,
                      const float* __restrict__ w2, const float* __restrict__ w3,
                      __half* d0, __half* d1, __half* d2, __half* d3)
{
    const int z = blockIdx.z;
    const float* s = (z == 0) ? w0 : (z == 1) ? w1 : (z == 2) ? w2 : w3;
    __half* d      = (z == 0) ? d0 : (z == 1) ? d1 : (z == 2) ? d2 : d3;
    const int i = blockIdx.x * blockDim.x + threadIdx.x;
    const float4 f = ((const float4*)s)[i];
    uint2 u;
    u.x = pack2(f.x, f.y);
    u.y = pack2(f.z, f.w);
    ((uint2*)d)[i] = u;
}

// ---------------------------------------------------------------------------
// fp16 GEMM: C = A(M,K) @ W^T(N,K) + bias.  Block 128x128, BK=32 halves,
// 256 thr, 8 warps (2m x 4n), warp tile 64x32, 3-stage cp.async pipeline.
// Permuted smem layout (logical 64B rows packed 2-per-128B physical row):
//   GOFF(r,c) = (r>>1)*128 + ((((r&1)*4 + c) ^ ((r>>1)&7)) * 16)   [bytes]
// -> conflict-free for both cp.async 16B writes and ldmatrix 8-row gathers.
// ---------------------------------------------------------------------------
#define GOFF(r, c) ((((r) >> 1) * 128) + ((((((r) & 1) * 4) + (c)) ^ (((r) >> 1) & 7)) * 16))
#define GEMM_NSTEPS 32   // 1024 / 32

__device__ __forceinline__ void gemm_h_core(
    const __half* __restrict__ A, const __half* __restrict__ W,
    const float* __restrict__ bias, void* __restrict__ Cout,
    int head_split, int m0, int n0)
{
    __shared__ __align__(16) char gsm[3 * 16384];   // 3 stages x (A 8KB + B 8KB)
    const uint32_t sb = smem_u32(gsm);

    const int tid  = threadIdx.x;
    const int lane = tid & 31;
    const int w    = tid >> 5;
    const int wm   = w >> 2;           // 0..1
    const int wn   = w & 3;            // 0..3

    float acc[4][4][4];
#pragma unroll
    for (int i = 0; i < 4; i++)
#pragma unroll
        for (int j = 0; j < 4; j++)
#pragma unroll
            for (int e = 0; e < 4; e++) acc[i][j][e] = 0.f;

    // staging: thread t<128 -> A row t; t>=128 -> B row t-128; 4 x 16B chunks
    const int srow = tid & 127;
    const __half* gsrc = (tid < 128) ? (A + (size_t)(m0 + srow) * D_MODEL)
                                     : (W + (size_t)(n0 + srow) * D_MODEL);
    uint32_t sdst[4];
#pragma unroll
    for (int c = 0; c < 4; c++)
        sdst[c] = sb + ((tid < 128) ? 0 : 8192) + GOFF(srow, c);

    // prologue: stages 0,1
#pragma unroll
    for (int st = 0; st < 2; st++) {
#pragma unroll
        for (int c = 0; c < 4; c++) CP16(sdst[c] + st * 16384, gsrc + st * 32 + c * 8);
        CP_COMMIT();
    }

    // fragment lane addresses (byte offsets within a stage's A/B region)
    uint32_t a_off[4][2], b_off[2][2];
#pragma unroll
    for (int i = 0; i < 4; i++) {
        const int r = wm * 64 + i * 16 + (lane & 7) + ((lane >> 3) & 1) * 8;
#pragma unroll
        for (int kt = 0; kt < 2; kt++) {
            const int c = 2 * kt + (lane >> 4);
            a_off[i][kt] = GOFF(r, c);
        }
    }
#pragma unroll
    for (int jp = 0; jp < 2; jp++) {
        const int r = wn * 32 + (2 * jp + ((lane >> 4) & 1)) * 8 + (lane & 7);
#pragma unroll
        for (int kt = 0; kt < 2; kt++) {
            const int c = 2 * kt + ((lane >> 3) & 1);
            b_off[jp][kt] = GOFF(r, c);
        }
    }

#pragma unroll 1
    for (int s = 0; s < GEMM_NSTEPS; s++) {
        if (s == GEMM_NSTEPS - 1) { CP_WAIT(0); } else { CP_WAIT(1); }
        __syncthreads();
        if (s + 2 < GEMM_NSTEPS) {
            const int st = (s + 2) % 3;
#pragma unroll
            for (int c = 0; c < 4; c++)
                CP16(sdst[c] + st * 16384, gsrc + (s + 2) * 32 + c * 8);
            CP_COMMIT();
        }

        const uint32_t ab = sb + (s % 3) * 16384;
        const uint32_t bb = ab + 8192;
#pragma unroll
        for (int kt = 0; kt < 2; kt++) {
            unsigned bf[4][2];
#pragma unroll
            for (int jp = 0; jp < 2; jp++) {
                unsigned t4[4];
                ldm_x4(t4, bb + b_off[jp][kt]);
                bf[2 * jp][0]     = t4[0]; bf[2 * jp][1]     = t4[1];
                bf[2 * jp + 1][0] = t4[2]; bf[2 * jp + 1][1] = t4[3];
            }
#pragma unroll
            for (int i = 0; i < 4; i++) {
                unsigned af[4];
                ldm_x4(af, ab + a_off[i][kt]);
#pragma unroll
                for (int j = 0; j < 4; j++) mma16(acc[i][j], af, bf[j]);
            }
        }
    }

    // ---- epilogue ----
#pragma unroll
    for (int i = 0; i < 4; i++) {
#pragma unroll
        for (int j = 0; j < 4; j++) {
            const int m = m0 + wm * 64 + i * 16 + (lane >> 2);
            const int n = n0 + wn * 32 + j * 8 + 2 * (lane & 3);
            const float2 bb2 = *(const float2*)(bias + n);
            const float v00 = acc[i][j][0] + bb2.x, v01 = acc[i][j][1] + bb2.y;
            const float v10 = acc[i][j][2] + bb2.x, v11 = acc[i][j][3] + bb2.y;
            if (head_split) {
                __half* C = (__half*)Cout;
                const int hh = n >> 6, d = n & 63;
                const int b0r = m >> 11, s0r = m & (SEQ - 1);
                const int b1r = (m + 8) >> 11, s1r = (m + 8) & (SEQ - 1);
                *(unsigned*)&C[(((size_t)b0r * NUM_HEADS + hh) * SEQ + s0r) * DEPTH + d] = pack2(v00, v01);
                *(unsigned*)&C[(((size_t)b1r * NUM_HEADS + hh) * SEQ + s1r) * DEPTH + d] = pack2(v10, v11);
            } else {
                float* C = (float*)Cout;
                float2 o0; o0.x = v00; o0.y = v01;
                float2 o1; o1.x = v10; o1.y = v11;
                *(float2*)&C[(size_t)m * D_MODEL + n] = o0;
                *(float2*)&C[(size_t)(m + 8) * D_MODEL + n] = o1;
            }
        }
    }
}

__global__ __launch_bounds__(256, 2) void gemm_qkv(
    const __half* __restrict__ qf, const __half* __restrict__ kf, const __half* __restrict__ vf,
    const __half* __restrict__ wq, const float* __restrict__ bq,
    const __half* __restrict__ wk, const float* __restrict__ bk,
    const __half* __restrict__ wv, const float* __restrict__ bv,
    __half* __restrict__ qh, __half* __restrict__ kh, __half* __restrict__ vh)
{
    const int z = blockIdx.z;
    const __half* A = (z == 0) ? qf : (z == 1) ? kf : vf;
    const __half* W = (z == 0) ? wq : (z == 1) ? wk : wv;
    const float*  B = (z == 0) ? bq : (z == 1) ? bk : bv;
    __half*       C = (z == 0) ? qh : (z == 1) ? kh : vh;
    gemm_h_core(A, W, B, C, 1, blockIdx.y * 128, blockIdx.x * 128);
}

__global__ __launch_bounds__(256, 2) void gemm_dense(
    const __half* __restrict__ A, const __half* __restrict__ W,
    const float* __restrict__ bias, float* __restrict__ C)
{
    gemm_h_core(A, W, bias, C, 0, blockIdx.y * 128, blockIdx.x * 128);
}

// ---------------------------------------------------------------------------
// fp16 FA2 causal attention. 256 thr (8 warps), 128 q/block (16 rows/warp),
// 64-key tiles, paired q-tiles (bx, 15-bx). Double-buffered cp.async K/V.
// K/V smem: 64 rows x 128B, swizzle KOFF(r,c) = r*128 + ((c ^ (r&7))*16).
// K -> QK^T B-frags via ldmatrix.x4; V -> PV B-frags via ldmatrix.x4.trans.
// P C-frags convert to PV A-frags by register packing (no shuffles/smem).
// ---------------------------------------------------------------------------
#define KOFF(r, c) ((r) * 128 + (((c) ^ ((r) & 7)) * 16))
#define ATTN_THREADS 256

__global__ __launch_bounds__(ATTN_THREADS, 2) void attn_h(
    const __half* __restrict__ Qg, const __half* __restrict__ Kg,
    const __half* __restrict__ Vg, __half* __restrict__ Og)
{
    __shared__ __align__(16) char asmm[2 * 16384];   // 2 bufs x (K 8KB + V 8KB)
    const uint32_t sb = smem_u32(asmm);

    const int tid  = threadIdx.x;
    const int lane = tid & 31;
    const int w    = tid >> 5;
    const int b    = blockIdx.z;
    const int h    = blockIdx.y;

    const size_t hoff = ((size_t)(b * NUM_HEADS + h) * SEQ) * DEPTH;
    const __half* kb = Kg + hoff;
    const __half* vb = Vg + hoff;

    const int r0 = lane >> 2;   // 0..7
    const int c0 = lane & 3;    // 0..3

    // staging: t<128 -> K, else V; thread covers row (t&127)>>1, chunks (t&1)*4..+3
    const int strow = (tid & 127) >> 1;
    const int stc0  = (tid & 1) * 4;
    const __half* stsrc = ((tid < 128) ? kb : vb) + (size_t)strow * DEPTH + stc0 * 8;
    uint32_t stdst[4];
#pragma unroll
    for (int i = 0; i < 4; i++)
        stdst[i] = sb + ((tid < 128) ? 0 : 8192) + KOFF(strow, stc0 + i);

    // fragment lane constants
    int rK[4];
#pragma unroll
    for (int jp = 0; jp < 4; jp++)
        rK[jp] = (2 * jp + ((lane >> 4) & 1)) * 8 + (lane & 7);
    const int hK  = (lane >> 3) & 1;             // K chunk-half bit
    const int rVl = (lane & 7) + ((lane >> 3) & 1) * 8;   // V row within kt*16
    const int cVb = (lane >> 4) & 1;             // V chunk add

#pragma unroll 1
    for (int pass = 0; pass < 2; pass++) {
        const int p  = pass ? (15 - (int)blockIdx.x) : (int)blockIdx.x;
        const int q0 = p * 128;

        // Q A-frags (direct global half2 loads, once per pass)
        unsigned qa[4][4];
        {
            const __half* qb = Qg + hoff + (size_t)(q0 + w * 16) * DEPTH;
#pragma unroll
            for (int kt = 0; kt < 4; kt++) {
                qa[kt][0] = *(const unsigned*)(qb + (size_t)(r0)     * DEPTH + kt * 16 + 2 * c0);
                qa[kt][1] = *(const unsigned*)(qb + (size_t)(r0 + 8) * DEPTH + kt * 16 + 2 * c0);
                qa[kt][2] = *(const unsigned*)(qb + (size_t)(r0)     * DEPTH + kt * 16 + 8 + 2 * c0);
                qa[kt][3] = *(const unsigned*)(qb + (size_t)(r0 + 8) * DEPTH + kt * 16 + 8 + 2 * c0);
            }
        }

        float o[8][4];
#pragma unroll
        for (int j = 0; j < 8; j++)
#pragma unroll
            for (int e = 0; e < 4; e++) o[j][e] = 0.f;
        float m0r = -1e30f, m1r = -1e30f;
        float l0r = 0.f,    l1r = 0.f;

        const int ntile = 2 * p + 2;
        const int qhiW  = q0 + w * 16 + 15;
        const int qrow  = q0 + w * 16 + r0;

        // prologue: stage tile 0 into buffer 0
#pragma unroll
        for (int i = 0; i < 4; i++) CP16(stdst[i], stsrc + i * 8);
        CP_COMMIT();

#pragma unroll 1
        for (int t = 0; t < ntile; t++) {
            CP_WAIT(0);
            __syncthreads();
            if (t + 1 < ntile) {
                const uint32_t bo = ((t + 1) & 1) * 16384;
                const __half* src = stsrc + (size_t)(t + 1) * 64 * DEPTH;
#pragma unroll
                for (int i = 0; i < 4; i++) CP16(stdst[i] + bo, src + i * 8);
                CP_COMMIT();
            }
            if (t * 64 > qhiW) continue;   // fully-masked tile for this warp

            const uint32_t kbuf = sb + (t & 1) * 16384;
            const uint32_t vbuf = kbuf + 8192;

            // ---- S = Q @ K^T ----
            float s[8][4];
#pragma unroll
            for (int j = 0; j < 8; j++)
#pragma unroll
                for (int e = 0; e < 4; e++) s[j][e] = 0.f;
#pragma unroll
            for (int kt = 0; kt < 4; kt++) {
#pragma unroll
                for (int jp = 0; jp < 4; jp++) {
                    unsigned t4[4];
                    ldm_x4(t4, kbuf + rK[jp] * 128 + (((2 * kt + hK) ^ (rK[jp] & 7)) << 4));
                    unsigned bf0[2] = {t4[0], t4[1]};
                    unsigned bf1[2] = {t4[2], t4[3]};
                    mma16(s[2 * jp],     qa[kt], bf0);
                    mma16(s[2 * jp + 1], qa[kt], bf1);
                }
            }

            // ---- scale + causal mask + online softmax ----
            const bool diag = (t >= ntile - 2);
            float mx0 = -1e30f, mx1 = -1e30f;
#pragma unroll
            for (int j = 0; j < 8; j++) {
#pragma unroll
                for (int e = 0; e < 4; e++) {
                    float vv = s[j][e] * 0.125f;
                    if (diag) {
                        const int key = t * 64 + j * 8 + 2 * (lane & 3) + (e & 1);
                        const int qq  = qrow + ((e >> 1) << 3);
                        if (key > qq) vv = -1e30f;
                    }
                    s[j][e] = vv;
                }
                mx0 = fmaxf(mx0, fmaxf(s[j][0], s[j][1]));
                mx1 = fmaxf(mx1, fmaxf(s[j][2], s[j][3]));
            }
            mx0 = fmaxf(mx0, __shfl_xor_sync(0xffffffffu, mx0, 1));
            mx0 = fmaxf(mx0, __shfl_xor_sync(0xffffffffu, mx0, 2));
            mx1 = fmaxf(mx1, __shfl_xor_sync(0xffffffffu, mx1, 1));
            mx1 = fmaxf(mx1, __shfl_xor_sync(0xffffffffu, mx1, 2));

            const float mn0 = fmaxf(m0r, mx0);
            const float mn1 = fmaxf(m1r, mx1);
            const float al0 = __expf(m0r - mn0);
            const float al1 = __expf(m1r - mn1);

            float ls0 = 0.f, ls1 = 0.f;
#pragma unroll
            for (int j = 0; j < 8; j++) {
                s[j][0] = __expf(s[j][0] - mn0); ls0 += s[j][0];
                s[j][1] = __expf(s[j][1] - mn0); ls0 += s[j][1];
                s[j][2] = __expf(s[j][2] - mn1); ls1 += s[j][2];
                s[j][3] = __expf(s[j][3] - mn1); ls1 += s[j][3];
            }
            ls0 += __shfl_xor_sync(0xffffffffu, ls0, 1);
            ls0 += __shfl_xor_sync(0xffffffffu, ls0, 2);
            ls1 += __shfl_xor_sync(0xffffffffu, ls1, 1);
            ls1 += __shfl_xor_sync(0xffffffffu, ls1, 2);

            l0r = l0r * al0 + ls0;
            l1r = l1r * al1 + ls1;
            m0r = mn0; m1r = mn1;

#pragma unroll
            for (int j = 0; j < 8; j++) {
                o[j][0] *= al0; o[j][1] *= al0;
                o[j][2] *= al1; o[j][3] *= al1;
            }

            // ---- O += P @ V : P A-frags are just packed S C-frags ----
#pragma unroll
            for (int kt = 0; kt < 4; kt++) {
                unsigned af[4];
                af[0] = pack2(s[2 * kt][0],     s[2 * kt][1]);
                af[1] = pack2(s[2 * kt][2],     s[2 * kt][3]);
                af[2] = pack2(s[2 * kt + 1][0], s[2 * kt + 1][1]);
                af[3] = pack2(s[2 * kt + 1][2], s[2 * kt + 1][3]);
                const int rV = kt * 16 + rVl;
#pragma unroll
                for (int jp = 0; jp < 4; jp++) {
                    unsigned t4[4];
                    ldm_x4_t(t4, vbuf + rV * 128 + (((2 * jp + cVb) ^ (rV & 7)) << 4));
                    unsigned bf0[2] = {t4[0], t4[1]};
                    unsigned bf1[2] = {t4[2], t4[3]};
                    mma16(o[2 * jp],     af, bf0);
                    mma16(o[2 * jp + 1], af, bf1);
                }
            }
        }

        // ---- epilogue: normalize, write half2 concat layout ----
        const float inv0 = 1.f / l0r;
        const float inv1 = 1.f / l1r;
        const int qq = q0 + w * 16 + r0;
#pragma unroll
        for (int j = 0; j < 8; j++) {
            const int col = j * 8 + 2 * (lane & 3);
            *(unsigned*)&Og[((size_t)(b * SEQ + qq))     * D_MODEL + h * DEPTH + col]
                = pack2(o[j][0] * inv0, o[j][1] * inv0);
            *(unsigned*)&Og[((size_t)(b * SEQ + qq + 8)) * D_MODEL + h * DEPTH + col]
                = pack2(o[j][2] * inv1, o[j][3] * inv1);
        }
        __syncthreads();   // buffers reused from t=0 next pass
    }
}

// ---------------------------------------------------------------------------
// Launch
// ---------------------------------------------------------------------------
extern "C" void kernel_launch(void* const* d_in, const int* in_sizes, int n_in,
                              void* d_out, int out_size)
{
    const float* v       = (const float*)d_in[0];
    const float* k       = (const float*)d_in[1];
    const float* q       = (const float*)d_in[2];
    // d_in[3] = mask (causal triu) -- analytic in attn kernel
    const float* wq_w    = (const float*)d_in[4];
    const float* wq_b    = (const float*)d_in[5];
    const float* wk_w    = (const float*)d_in[6];
    const float* wk_b    = (const float*)d_in[7];
    const float* wv_w    = (const float*)d_in[8];
    const float* wv_b    = (const float*)d_in[9];
    const float* dense_w = (const float*)d_in[10];
    const float* dense_b = (const float*)d_in[11];
    float* out = (float*)d_out;

    __half *qf, *kf, *vf, *wq, *wk, *wv, *wd, *qh, *kh, *vh, *att;
    cudaGetSymbolAddress((void**)&qf,  g_qf);
    cudaGetSymbolAddress((void**)&kf,  g_kf);
    cudaGetSymbolAddress((void**)&vf,  g_vf);
    cudaGetSymbolAddress((void**)&wq,  g_wq);
    cudaGetSymbolAddress((void**)&wk,  g_wk);
    cudaGetSymbolAddress((void**)&wv,  g_wv);
    cudaGetSymbolAddress((void**)&wd,  g_wd);
    cudaGetSymbolAddress((void**)&qh,  g_qh);
    cudaGetSymbolAddress((void**)&kh,  g_kh);
    cudaGetSymbolAddress((void**)&vh,  g_vh);
    cudaGetSymbolAddress((void**)&att, g_att);

    // 1) f32 -> f16 conversions
    cvt_qkv<<<dim3(M_ROWS * D_MODEL / 4 / 256, 1, 3), 256>>>(q, k, v, qf, kf, vf);
    cvt_w<<<dim3(D_MODEL * D_MODEL / 4 / 256, 1, 4), 256>>>(wq_w, wk_w, wv_w, dense_w,
                                                            wq, wk, wv, wd);

    // 2) Q/K/V projections (head-split half output)
    const dim3 pgrid(D_MODEL / 128, M_ROWS / 128, 3);   // (8, 32, 3)
    gemm_qkv<<<pgrid, 256>>>(qf, kf, vf, wq, wq_b, wk, wk_b, wv, wv_b, qh, kh, vh);

    // 3) attention (half in, half out)
    const dim3 agrid(SEQ / 256, NUM_HEADS, BATCH);      // (8, 16, 2) paired tiles
    attn_h<<<agrid, ATTN_THREADS>>>(qh, kh, vh, att);

    // 4) dense (half in, f32 out)
    const dim3 dgrid(D_MODEL / 128, M_ROWS / 128);      // (8, 32)
    gemm_dense<<<dgrid, 256>>>(att, wd, dense_b, out);
}

// round 11
// speedup vs baseline: 2.1853x; 1.0058x over previous
#include <cuda_runtime.h>
#include <cuda_fp16.h>
#include <cstddef>
#include <cstdint>

#define D_MODEL   1024
#define NUM_HEADS 16
#define DEPTH     64
#define BATCH     2
#define SEQ       2048
#define M_ROWS    (BATCH * SEQ)   // 4096

// Q-path scale: (1/sqrt(64)) * log2(e)  — folds softmax scaling + exp->ex2
#define QSCALE 0.18033688011112042f

// ---------------------------------------------------------------------------
// Scratch (all fp16 intermediates; f32 only for biases & final output)
// ---------------------------------------------------------------------------
__device__ __half g_qf[M_ROWS * D_MODEL];    // converted inputs
__device__ __half g_kf[M_ROWS * D_MODEL];
__device__ __half g_vf[M_ROWS * D_MODEL];
__device__ __half g_wq[D_MODEL * D_MODEL];   // converted weights (wq pre-scaled)
__device__ __half g_wk[D_MODEL * D_MODEL];
__device__ __half g_wv[D_MODEL * D_MODEL];
__device__ __half g_wd[D_MODEL * D_MODEL];
__device__ __half g_qh[BATCH * NUM_HEADS * SEQ * DEPTH];   // projections [B,H,S,64]
__device__ __half g_kh[BATCH * NUM_HEADS * SEQ * DEPTH];
__device__ __half g_vh[BATCH * NUM_HEADS * SEQ * DEPTH];
__device__ __half g_att[M_ROWS * D_MODEL];   // attention out, concat layout

// ---------------------------------------------------------------------------
// Helpers
// ---------------------------------------------------------------------------
__device__ __forceinline__ uint32_t smem_u32(const void* p) {
    uint32_t a;
    asm("{ .reg .u64 t; cvta.to.shared.u64 t, %1; cvt.u32.u64 %0, t; }" : "=r"(a) : "l"(p));
    return a;
}

__device__ __forceinline__ unsigned pack2(float a, float b) {
    __half2 h = __floats2half2_rn(a, b);   // low half = a
    return *reinterpret_cast<unsigned*>(&h);
}

__device__ __forceinline__ float ex2f(float x) {
    float y;
    asm("ex2.approx.f32 %0, %1;" : "=f"(y) : "f"(x));
    return y;
}

__device__ __forceinline__ void mma16(float* c, const unsigned* a, const unsigned* b) {
    asm volatile(
        "mma.sync.aligned.m16n8k16.row.col.f32.f16.f16.f32 "
        "{%0,%1,%2,%3},{%4,%5,%6,%7},{%8,%9},{%0,%1,%2,%3};"
        : "+f"(c[0]), "+f"(c[1]), "+f"(c[2]), "+f"(c[3])
        : "r"(a[0]), "r"(a[1]), "r"(a[2]), "r"(a[3]), "r"(b[0]), "r"(b[1]));
}

__device__ __forceinline__ void ldm_x4(unsigned* d, uint32_t addr) {
    asm volatile("ldmatrix.sync.aligned.m8n8.x4.shared.b16 {%0,%1,%2,%3}, [%4];"
                 : "=r"(d[0]), "=r"(d[1]), "=r"(d[2]), "=r"(d[3]) : "r"(addr));
}
__device__ __forceinline__ void ldm_x4_t(unsigned* d, uint32_t addr) {
    asm volatile("ldmatrix.sync.aligned.m8n8.x4.trans.shared.b16 {%0,%1,%2,%3}, [%4];"
                 : "=r"(d[0]), "=r"(d[1]), "=r"(d[2]), "=r"(d[3]) : "r"(addr));
}

#define CP16(dst, src) \
    asm volatile("cp.async.cg.shared.global [%0], [%1], 16;" :: "r"(dst), "l"(src) : "memory")
#define CP_COMMIT() asm volatile("cp.async.commit_group;" ::: "memory")
#define CP_WAIT(n)  asm volatile("cp.async.wait_group %0;" :: "n"(n) : "memory")

// ---------------------------------------------------------------------------
// Conversion kernels (f32 -> f16), vectorized
// ---------------------------------------------------------------------------
__global__ void cvt_qkv(const float* __restrict__ q, const float* __restrict__ k,
                        const float* __restrict__ v,
                        __half* dq, __half* dk, __half* dv)
{
    const int z = blockIdx.z;
    const float* s = (z == 0) ? q : (z == 1) ? k : v;
    __half* d      = (z == 0) ? dq : (z == 1) ? dk : dv;
    const int i = blockIdx.x * blockDim.x + threadIdx.x;   // per float4
    const float4 f = ((const float4*)s)[i];
    uint2 u;
    u.x = pack2(f.x, f.y);
    u.y = pack2(f.z, f.w);
    ((uint2*)d)[i] = u;
}

__global__ void cvt_w(const float* __restrict__ w0, const float* __restrict__ w1,
                      const float* __restrict__ w2, const float* __restrict__ w3,
                      __half* d0, __half* d1, __half* d2, __half* d3)
{
    const int z = blockIdx.z;
    const float* s = (z == 0) ? w0 : (z == 1) ? w1 : (z == 2) ? w2 : w3;
    __half* d      = (z == 0) ? d0 : (z == 1) ? d1 : (z == 2) ? d2 : d3;
    const float sc = (z == 0) ? QSCALE : 1.0f;   // fold softmax scale into wq
    const int i = blockIdx.x * blockDim.x + threadIdx.x;
    const float4 f = ((const float4*)s)[i];
    uint2 u;
    u.x = pack2(f.x * sc, f.y * sc);
    u.y = pack2(f.z * sc, f.w * sc);
    ((uint2*)d)[i] = u;
}

// ---------------------------------------------------------------------------
// fp16 GEMM: C = A(M,K) @ W^T(N,K) + bias*bscale.  Block 128x128, BK=32,
// 256 thr, 8 warps (2m x 4n), warp tile 64x32, 3-stage cp.async pipeline.
//   GOFF(r,c) = (r>>1)*128 + ((((r&1)*4 + c) ^ ((r>>1)&7)) * 16)   [bytes]
// ---------------------------------------------------------------------------
#define GOFF(r, c) ((((r) >> 1) * 128) + ((((((r) & 1) * 4) + (c)) ^ (((r) >> 1) & 7)) * 16))
#define GEMM_NSTEPS 32   // 1024 / 32

__device__ __forceinline__ void gemm_h_core(
    const __half* __restrict__ A, const __half* __restrict__ W,
    const float* __restrict__ bias, void* __restrict__ Cout,
    int head_split, int m0, int n0, float bscale)
{
    __shared__ __align__(16) char gsm[3 * 16384];   // 3 stages x (A 8KB + B 8KB)
    const uint32_t sb = smem_u32(gsm);

    const int tid  = threadIdx.x;
    const int lane = tid & 31;
    const int w    = tid >> 5;
    const int wm   = w >> 2;           // 0..1
    const int wn   = w & 3;            // 0..3

    float acc[4][4][4];
#pragma unroll
    for (int i = 0; i < 4; i++)
#pragma unroll
        for (int j = 0; j < 4; j++)
#pragma unroll
            for (int e = 0; e < 4; e++) acc[i][j][e] = 0.f;

    const int srow = tid & 127;
    const __half* gsrc = (tid < 128) ? (A + (size_t)(m0 + srow) * D_MODEL)
                                     : (W + (size_t)(n0 + srow) * D_MODEL);
    uint32_t sdst[4];
#pragma unroll
    for (int c = 0; c < 4; c++)
        sdst[c] = sb + ((tid < 128) ? 0 : 8192) + GOFF(srow, c);

#pragma unroll
    for (int st = 0; st < 2; st++) {
#pragma unroll
        for (int c = 0; c < 4; c++) CP16(sdst[c] + st * 16384, gsrc + st * 32 + c * 8);
        CP_COMMIT();
    }

    uint32_t a_off[4][2], b_off[2][2];
#pragma unroll
    for (int i = 0; i < 4; i++) {
        const int r = wm * 64 + i * 16 + (lane & 7) + ((lane >> 3) & 1) * 8;
#pragma unroll
        for (int kt = 0; kt < 2; kt++) {
            const int c = 2 * kt + (lane >> 4);
            a_off[i][kt] = GOFF(r, c);
        }
    }
#pragma unroll
    for (int jp = 0; jp < 2; jp++) {
        const int r = wn * 32 + (2 * jp + ((lane >> 4) & 1)) * 8 + (lane & 7);
#pragma unroll
        for (int kt = 0; kt < 2; kt++) {
            const int c = 2 * kt + ((lane >> 3) & 1);
            b_off[jp][kt] = GOFF(r, c);
        }
    }

#pragma unroll 1
    for (int s = 0; s < GEMM_NSTEPS; s++) {
        if (s == GEMM_NSTEPS - 1) { CP_WAIT(0); } else { CP_WAIT(1); }
        __syncthreads();
        if (s + 2 < GEMM_NSTEPS) {
            const int st = (s + 2) % 3;
#pragma unroll
            for (int c = 0; c < 4; c++)
                CP16(sdst[c] + st * 16384, gsrc + (s + 2) * 32 + c * 8);
            CP_COMMIT();
        }

        const uint32_t ab = sb + (s % 3) * 16384;
        const uint32_t bb = ab + 8192;
#pragma unroll
        for (int kt = 0; kt < 2; kt++) {
            unsigned bf[4][2];
#pragma unroll
            for (int jp = 0; jp < 2; jp++) {
                unsigned t4[4];
                ldm_x4(t4, bb + b_off[jp][kt]);
                bf[2 * jp][0]     = t4[0]; bf[2 * jp][1]     = t4[1];
                bf[2 * jp + 1][0] = t4[2]; bf[2 * jp + 1][1] = t4[3];
            }
#pragma unroll
            for (int i = 0; i < 4; i++) {
                unsigned af[4];
                ldm_x4(af, ab + a_off[i][kt]);
#pragma unroll
                for (int j = 0; j < 4; j++) mma16(acc[i][j], af, bf[j]);
            }
        }
    }

    // ---- epilogue ----
#pragma unroll
    for (int i = 0; i < 4; i++) {
#pragma unroll
        for (int j = 0; j < 4; j++) {
            const int m = m0 + wm * 64 + i * 16 + (lane >> 2);
            const int n = n0 + wn * 32 + j * 8 + 2 * (lane & 3);
            const float2 bb2 = *(const float2*)(bias + n);
            const float bx = bb2.x * bscale, by = bb2.y * bscale;
            const float v00 = acc[i][j][0] + bx, v01 = acc[i][j][1] + by;
            const float v10 = acc[i][j][2] + bx, v11 = acc[i][j][3] + by;
            if (head_split) {
                __half* C = (__half*)Cout;
                const int hh = n >> 6, d = n & 63;
                const int b0r = m >> 11, s0r = m & (SEQ - 1);
                const int b1r = (m + 8) >> 11, s1r = (m + 8) & (SEQ - 1);
                *(unsigned*)&C[(((size_t)b0r * NUM_HEADS + hh) * SEQ + s0r) * DEPTH + d] = pack2(v00, v01);
                *(unsigned*)&C[(((size_t)b1r * NUM_HEADS + hh) * SEQ + s1r) * DEPTH + d] = pack2(v10, v11);
            } else {
                float* C = (float*)Cout;
                float2 o0; o0.x = v00; o0.y = v01;
                float2 o1; o1.x = v10; o1.y = v11;
                *(float2*)&C[(size_t)m * D_MODEL + n] = o0;
                *(float2*)&C[(size_t)(m + 8) * D_MODEL + n] = o1;
            }
        }
    }
}

__global__ __launch_bounds__(256, 2) void gemm_qkv(
    const __half* __restrict__ qf, const __half* __restrict__ kf, const __half* __restrict__ vf,
    const __half* __restrict__ wq, const float* __restrict__ bq,
    const __half* __restrict__ wk, const float* __restrict__ bk,
    const __half* __restrict__ wv, const float* __restrict__ bv,
    __half* __restrict__ qh, __half* __restrict__ kh, __half* __restrict__ vh)
{
    const int z = blockIdx.z;
    const __half* A = (z == 0) ? qf : (z == 1) ? kf : vf;
    const __half* W = (z == 0) ? wq : (z == 1) ? wk : wv;
    const float*  B = (z == 0) ? bq : (z == 1) ? bk : bv;
    __half*       C = (z == 0) ? qh : (z == 1) ? kh : vh;
    const float bs  = (z == 0) ? QSCALE : 1.0f;
    gemm_h_core(A, W, B, C, 1, blockIdx.y * 128, blockIdx.x * 128, bs);
}

__global__ __launch_bounds__(256, 2) void gemm_dense(
    const __half* __restrict__ A, const __half* __restrict__ W,
    const float* __restrict__ bias, float* __restrict__ C)
{
    gemm_h_core(A, W, bias, C, 0, blockIdx.y * 128, blockIdx.x * 128, 1.0f);
}

// ---------------------------------------------------------------------------
// fp16 FA2 causal attention, log2-domain softmax (Q pre-scaled by QSCALE).
// 256 thr (8 warps), 128 q/block (16 rows/warp), 64-key tiles,
// paired q-tiles (bx, 15-bx), double-buffered cp.async K/V.
// ---------------------------------------------------------------------------
#define KOFF(r, c) ((r) * 128 + (((c) ^ ((r) & 7)) * 16))
#define ATTN_THREADS 256

__global__ __launch_bounds__(ATTN_THREADS, 2) void attn_h(
    const __half* __restrict__ Qg, const __half* __restrict__ Kg,
    const __half* __restrict__ Vg, __half* __restrict__ Og)
{
    __shared__ __align__(16) char asmm[2 * 16384];   // 2 bufs x (K 8KB + V 8KB)
    const uint32_t sb = smem_u32(asmm);

    const int tid  = threadIdx.x;
    const int lane = tid & 31;
    const int w    = tid >> 5;
    const int b    = blockIdx.z;
    const int h    = blockIdx.y;

    const size_t hoff = ((size_t)(b * NUM_HEADS + h) * SEQ) * DEPTH;
    const __half* kb = Kg + hoff;
    const __half* vb = Vg + hoff;

    const int r0 = lane >> 2;   // 0..7
    const int c0 = lane & 3;    // 0..3

    const int strow = (tid & 127) >> 1;
    const int stc0  = (tid & 1) * 4;
    const __half* stsrc = ((tid < 128) ? kb : vb) + (size_t)strow * DEPTH + stc0 * 8;
    uint32_t stdst[4];
#pragma unroll
    for (int i = 0; i < 4; i++)
        stdst[i] = sb + ((tid < 128) ? 0 : 8192) + KOFF(strow, stc0 + i);

    int rK[4];
#pragma unroll
    for (int jp = 0; jp < 4; jp++)
        rK[jp] = (2 * jp + ((lane >> 4) & 1)) * 8 + (lane & 7);
    const int hK  = (lane >> 3) & 1;
    const int rVl = (lane & 7) + ((lane >> 3) & 1) * 8;
    const int cVb = (lane >> 4) & 1;

#pragma unroll 1
    for (int pass = 0; pass < 2; pass++) {
        const int p  = pass ? (15 - (int)blockIdx.x) : (int)blockIdx.x;
        const int q0 = p * 128;

        unsigned qa[4][4];
        {
            const __half* qb = Qg + hoff + (size_t)(q0 + w * 16) * DEPTH;
#pragma unroll
            for (int kt = 0; kt < 4; kt++) {
                qa[kt][0] = *(const unsigned*)(qb + (size_t)(r0)     * DEPTH + kt * 16 + 2 * c0);
                qa[kt][1] = *(const unsigned*)(qb + (size_t)(r0 + 8) * DEPTH + kt * 16 + 2 * c0);
                qa[kt][2] = *(const unsigned*)(qb + (size_t)(r0)     * DEPTH + kt * 16 + 8 + 2 * c0);
                qa[kt][3] = *(const unsigned*)(qb + (size_t)(r0 + 8) * DEPTH + kt * 16 + 8 + 2 * c0);
            }
        }

        float o[8][4];
#pragma unroll
        for (int j = 0; j < 8; j++)
#pragma unroll
            for (int e = 0; e < 4; e++) o[j][e] = 0.f;
        float m0r = -1e30f, m1r = -1e30f;
        float l0r = 0.f,    l1r = 0.f;

        const int ntile = 2 * p + 2;
        const int qhiW  = q0 + w * 16 + 15;
        const int qrow  = q0 + w * 16 + r0;

#pragma unroll
        for (int i = 0; i < 4; i++) CP16(stdst[i], stsrc + i * 8);
        CP_COMMIT();

#pragma unroll 1
        for (int t = 0; t < ntile; t++) {
            CP_WAIT(0);
            __syncthreads();
            if (t + 1 < ntile) {
                const uint32_t bo = ((t + 1) & 1) * 16384;
                const __half* src = stsrc + (size_t)(t + 1) * 64 * DEPTH;
#pragma unroll
                for (int i = 0; i < 4; i++) CP16(stdst[i] + bo, src + i * 8);
                CP_COMMIT();
            }
            if (t * 64 > qhiW) continue;

            const uint32_t kbuf = sb + (t & 1) * 16384;
            const uint32_t vbuf = kbuf + 8192;

            // ---- S = Q @ K^T  (scores already in log2 domain) ----
            float s[8][4];
#pragma unroll
            for (int j = 0; j < 8; j++)
#pragma unroll
                for (int e = 0; e < 4; e++) s[j][e] = 0.f;
#pragma unroll
            for (int kt = 0; kt < 4; kt++) {
#pragma unroll
                for (int jp = 0; jp < 4; jp++) {
                    unsigned t4[4];
                    ldm_x4(t4, kbuf + rK[jp] * 128 + (((2 * kt + hK) ^ (rK[jp] & 7)) << 4));
                    unsigned bf0[2] = {t4[0], t4[1]};
                    unsigned bf1[2] = {t4[2], t4[3]};
                    mma16(s[2 * jp],     qa[kt], bf0);
                    mma16(s[2 * jp + 1], qa[kt], bf1);
                }
            }

            // ---- causal mask + online softmax (base-2) ----
            const bool diag = (t >= ntile - 2);
            float mx0 = -1e30f, mx1 = -1e30f;
#pragma unroll
            for (int j = 0; j < 8; j++) {
                if (diag) {
#pragma unroll
                    for (int e = 0; e < 4; e++) {
                        const int key = t * 64 + j * 8 + 2 * (lane & 3) + (e & 1);
                        const int qq  = qrow + ((e >> 1) << 3);
                        if (key > qq) s[j][e] = -1e30f;
                    }
                }
                mx0 = fmaxf(mx0, fmaxf(s[j][0], s[j][1]));
                mx1 = fmaxf(mx1, fmaxf(s[j][2], s[j][3]));
            }
            mx0 = fmaxf(mx0, __shfl_xor_sync(0xffffffffu, mx0, 1));
            mx0 = fmaxf(mx0, __shfl_xor_sync(0xffffffffu, mx0, 2));
            mx1 = fmaxf(mx1, __shfl_xor_sync(0xffffffffu, mx1, 1));
            mx1 = fmaxf(mx1, __shfl_xor_sync(0xffffffffu, mx1, 2));

            const float mn0 = fmaxf(m0r, mx0);
            const float mn1 = fmaxf(m1r, mx1);
            const float al0 = ex2f(m0r - mn0);
            const float al1 = ex2f(m1r - mn1);

            float ls0 = 0.f, ls1 = 0.f;
#pragma unroll
            for (int j = 0; j < 8; j++) {
                s[j][0] = ex2f(s[j][0] - mn0); ls0 += s[j][0];
                s[j][1] = ex2f(s[j][1] - mn0); ls0 += s[j][1];
                s[j][2] = ex2f(s[j][2] - mn1); ls1 += s[j][2];
                s[j][3] = ex2f(s[j][3] - mn1); ls1 += s[j][3];
            }
            ls0 += __shfl_xor_sync(0xffffffffu, ls0, 1);
            ls0 += __shfl_xor_sync(0xffffffffu, ls0, 2);
            ls1 += __shfl_xor_sync(0xffffffffu, ls1, 1);
            ls1 += __shfl_xor_sync(0xffffffffu, ls1, 2);

            l0r = l0r * al0 + ls0;
            l1r = l1r * al1 + ls1;
            m0r = mn0; m1r = mn1;

#pragma unroll
            for (int j = 0; j < 8; j++) {
                o[j][0] *= al0; o[j][1] *= al0;
                o[j][2] *= al1; o[j][3] *= al1;
            }

            // ---- O += P @ V : P A-frags are packed S C-frags ----
#pragma unroll
            for (int kt = 0; kt < 4; kt++) {
                unsigned af[4];
                af[0] = pack2(s[2 * kt][0],     s[2 * kt][1]);
                af[1] = pack2(s[2 * kt][2],     s[2 * kt][3]);
                af[2] = pack2(s[2 * kt + 1][0], s[2 * kt + 1][1]);
                af[3] = pack2(s[2 * kt + 1][2], s[2 * kt + 1][3]);
                const int rV = kt * 16 + rVl;
#pragma unroll
                for (int jp = 0; jp < 4; jp++) {
                    unsigned t4[4];
                    ldm_x4_t(t4, vbuf + rV * 128 + (((2 * jp + cVb) ^ (rV & 7)) << 4));
                    unsigned bf0[2] = {t4[0], t4[1]};
                    unsigned bf1[2] = {t4[2], t4[3]};
                    mma16(o[2 * jp],     af, bf0);
                    mma16(o[2 * jp + 1], af, bf1);
                }
            }
        }

        // ---- epilogue ----
        const float inv0 = 1.f / l0r;
        const float inv1 = 1.f / l1r;
        const int qq = q0 + w * 16 + r0;
#pragma unroll
        for (int j = 0; j < 8; j++) {
            const int col = j * 8 + 2 * (lane & 3);
            *(unsigned*)&Og[((size_t)(b * SEQ + qq))     * D_MODEL + h * DEPTH + col]
                = pack2(o[j][0] * inv0, o[j][1] * inv0);
            *(unsigned*)&Og[((size_t)(b * SEQ + qq + 8)) * D_MODEL + h * DEPTH + col]
                = pack2(o[j][2] * inv1, o[j][3] * inv1);
        }
        __syncthreads();   // buffers reused from t=0 next pass
    }
}

// ---------------------------------------------------------------------------
// Launch
// ---------------------------------------------------------------------------
extern "C" void kernel_launch(void* const* d_in, const int* in_sizes, int n_in,
                              void* d_out, int out_size)
{
    const float* v       = (const float*)d_in[0];
    const float* k       = (const float*)d_in[1];
    const float* q       = (const float*)d_in[2];
    // d_in[3] = mask (causal triu) -- analytic in attn kernel
    const float* wq_w    = (const float*)d_in[4];
    const float* wq_b    = (const float*)d_in[5];
    const float* wk_w    = (const float*)d_in[6];
    const float* wk_b    = (const float*)d_in[7];
    const float* wv_w    = (const float*)d_in[8];
    const float* wv_b    = (const float*)d_in[9];
    const float* dense_w = (const float*)d_in[10];
    const float* dense_b = (const float*)d_in[11];
    float* out = (float*)d_out;

    __half *qf, *kf, *vf, *wq, *wk, *wv, *wd, *qh, *kh, *vh, *att;
    cudaGetSymbolAddress((void**)&qf,  g_qf);
    cudaGetSymbolAddress((void**)&kf,  g_kf);
    cudaGetSymbolAddress((void**)&vf,  g_vf);
    cudaGetSymbolAddress((void**)&wq,  g_wq);
    cudaGetSymbolAddress((void**)&wk,  g_wk);
    cudaGetSymbolAddress((void**)&wv,  g_wv);
    cudaGetSymbolAddress((void**)&wd,  g_wd);
    cudaGetSymbolAddress((void**)&qh,  g_qh);
    cudaGetSymbolAddress((void**)&kh,  g_kh);
    cudaGetSymbolAddress((void**)&vh,  g_vh);
    cudaGetSymbolAddress((void**)&att, g_att);

    // 1) f32 -> f16 conversions (wq pre-scaled by QSCALE)
    cvt_qkv<<<dim3(M_ROWS * D_MODEL / 4 / 256, 1, 3), 256>>>(q, k, v, qf, kf, vf);
    cvt_w<<<dim3(D_MODEL * D_MODEL / 4 / 256, 1, 4), 256>>>(wq_w, wk_w, wv_w, dense_w,
                                                            wq, wk, wv, wd);

    // 2) Q/K/V projections (head-split half output)
    const dim3 pgrid(D_MODEL / 128, M_ROWS / 128, 3);   // (8, 32, 3)
    gemm_qkv<<<pgrid, 256>>>(qf, kf, vf, wq, wq_b, wk, wk_b, wv, wv_b, qh, kh, vh);

    // 3) attention (half in, half out)
    const dim3 agrid(SEQ / 256, NUM_HEADS, BATCH);      // (8, 16, 2) paired tiles
    attn_h<<<agrid, ATTN_THREADS>>>(qh, kh, vh, att);

    // 4) dense (half in, f32 out)
    const dim3 dgrid(D_MODEL / 128, M_ROWS / 128);      // (8, 32)
    gemm_dense<<<dgrid, 256>>>(att, wd, dense_b, out);
}

// round 12
// speedup vs baseline: 2.1998x; 1.0066x over previous
#include <cuda_runtime.h>
#include <cuda_fp16.h>
#include <cstddef>
#include <cstdint>

#define D_MODEL   1024
#define NUM_HEADS 16
#define DEPTH     64
#define BATCH     2
#define SEQ       2048
#define M_ROWS    (BATCH * SEQ)   // 4096

// Q-path scale: (1/sqrt(64)) * log2(e)  — folds softmax scaling + exp->ex2
#define QSCALE 0.18033688011112042f

// ---------------------------------------------------------------------------
// Scratch (all fp16 intermediates; f32 only for biases & final output)
// ---------------------------------------------------------------------------
__device__ __half g_qf[M_ROWS * D_MODEL];    // converted inputs
__device__ __half g_kf[M_ROWS * D_MODEL];
__device__ __half g_vf[M_ROWS * D_MODEL];
__device__ __half g_wq[D_MODEL * D_MODEL];   // converted weights (wq pre-scaled)
__device__ __half g_wk[D_MODEL * D_MODEL];
__device__ __half g_wv[D_MODEL * D_MODEL];
__device__ __half g_wd[D_MODEL * D_MODEL];
__device__ __half g_qh[BATCH * NUM_HEADS * SEQ * DEPTH];   // projections [B,H,S,64]
__device__ __half g_kh[BATCH * NUM_HEADS * SEQ * DEPTH];
__device__ __half g_vh[BATCH * NUM_HEADS * SEQ * DEPTH];
__device__ __half g_att[M_ROWS * D_MODEL];   // attention out, concat layout

// ---------------------------------------------------------------------------
// Helpers
// ---------------------------------------------------------------------------
__device__ __forceinline__ uint32_t smem_u32(const void* p) {
    uint32_t a;
    asm("{ .reg .u64 t; cvta.to.shared.u64 t, %1; cvt.u32.u64 %0, t; }" : "=r"(a) : "l"(p));
    return a;
}

__device__ __forceinline__ unsigned pack2(float a, float b) {
    __half2 h = __floats2half2_rn(a, b);   // low half = a
    return *reinterpret_cast<unsigned*>(&h);
}

__device__ __forceinline__ float ex2f(float x) {
    float y;
    asm("ex2.approx.f32 %0, %1;" : "=f"(y) : "f"(x));
    return y;
}

// paired exponential: ex2 on both halves of a packed half2
__device__ __forceinline__ unsigned h2ex2(unsigned x) {
    unsigned y;
    asm("ex2.approx.f16x2 %0, %1;" : "=r"(y) : "r"(x));
    return y;
}

__device__ __forceinline__ void mma16(float* c, const unsigned* a, const unsigned* b) {
    asm volatile(
        "mma.sync.aligned.m16n8k16.row.col.f32.f16.f16.f32 "
        "{%0,%1,%2,%3},{%4,%5,%6,%7},{%8,%9},{%0,%1,%2,%3};"
        : "+f"(c[0]), "+f"(c[1]), "+f"(c[2]), "+f"(c[3])
        : "r"(a[0]), "r"(a[1]), "r"(a[2]), "r"(a[3]), "r"(b[0]), "r"(b[1]));
}

__device__ __forceinline__ void ldm_x4(unsigned* d, uint32_t addr) {
    asm volatile("ldmatrix.sync.aligned.m8n8.x4.shared.b16 {%0,%1,%2,%3}, [%4];"
                 : "=r"(d[0]), "=r"(d[1]), "=r"(d[2]), "=r"(d[3]) : "r"(addr));
}
__device__ __forceinline__ void ldm_x4_t(unsigned* d, uint32_t addr) {
    asm volatile("ldmatrix.sync.aligned.m8n8.x4.trans.shared.b16 {%0,%1,%2,%3}, [%4];"
                 : "=r"(d[0]), "=r"(d[1]), "=r"(d[2]), "=r"(d[3]) : "r"(addr));
}

#define CP16(dst, src) \
    asm volatile("cp.async.cg.shared.global [%0], [%1], 16;" :: "r"(dst), "l"(src) : "memory")
#define CP_COMMIT() asm volatile("cp.async.commit_group;" ::: "memory")
#define CP_WAIT(n)  asm volatile("cp.async.wait_group %0;" :: "n"(n) : "memory")

// ---------------------------------------------------------------------------
// Conversion kernel (f32 -> f16): z 0..2 inputs (q,k,v), 3..6 weights.
// wq (z==3) pre-scaled by QSCALE.
// ---------------------------------------------------------------------------
__global__ void cvt_all(const float* __restrict__ q, const float* __restrict__ k,
                        const float* __restrict__ v,
                        const float* __restrict__ w0, const float* __restrict__ w1,
                        const float* __restrict__ w2, const float* __restrict__ w3,
                        __half* dq, __half* dk, __half* dv,
                        __half* d0, __half* d1, __half* d2, __half* d3)
{
    const int z = blockIdx.z;
    const int n = (z < 3) ? (M_ROWS * D_MODEL / 4) : (D_MODEL * D_MODEL / 4);
    const int i = blockIdx.x * blockDim.x + threadIdx.x;
    if (i >= n) return;
    const float* s;
    __half* d;
    float sc = 1.0f;
    switch (z) {
        case 0: s = q;  d = dq; break;
        case 1: s = k;  d = dk; break;
        case 2: s = v;  d = dv; break;
        case 3: s = w0; d = d0; sc = QSCALE; break;
        case 4: s = w1; d = d1; break;
        case 5: s = w2; d = d2; break;
        default: s = w3; d = d3; break;
    }
    const float4 f = ((const float4*)s)[i];
    uint2 u;
    u.x = pack2(f.x * sc, f.y * sc);
    u.y = pack2(f.z * sc, f.w * sc);
    ((uint2*)d)[i] = u;
}

// ---------------------------------------------------------------------------
// fp16 GEMM: C = A(M,K) @ W^T(N,K) + bias*bscale.  Block 128x128, BK=32,
// 256 thr, 8 warps (2m x 4n), warp tile 64x32, 3-stage cp.async pipeline.
//   GOFF(r,c) = (r>>1)*128 + ((((r&1)*4 + c) ^ ((r>>1)&7)) * 16)   [bytes]
// ---------------------------------------------------------------------------
#define GOFF(r, c) ((((r) >> 1) * 128) + ((((((r) & 1) * 4) + (c)) ^ (((r) >> 1) & 7)) * 16))
#define GEMM_NSTEPS 32   // 1024 / 32

__device__ __forceinline__ void gemm_h_core(
    const __half* __restrict__ A, const __half* __restrict__ W,
    const float* __restrict__ bias, void* __restrict__ Cout,
    int head_split, int m0, int n0, float bscale)
{
    __shared__ __align__(16) char gsm[3 * 16384];   // 3 stages x (A 8KB + B 8KB)
    const uint32_t sb = smem_u32(gsm);

    const int tid  = threadIdx.x;
    const int lane = tid & 31;
    const int w    = tid >> 5;
    const int wm   = w >> 2;           // 0..1
    const int wn   = w & 3;            // 0..3

    float acc[4][4][4];
#pragma unroll
    for (int i = 0; i < 4; i++)
#pragma unroll
        for (int j = 0; j < 4; j++)
#pragma unroll
            for (int e = 0; e < 4; e++) acc[i][j][e] = 0.f;

    const int srow = tid & 127;
    const __half* gsrc = (tid < 128) ? (A + (size_t)(m0 + srow) * D_MODEL)
                                     : (W + (size_t)(n0 + srow) * D_MODEL);
    uint32_t sdst[4];
#pragma unroll
    for (int c = 0; c < 4; c++)
        sdst[c] = sb + ((tid < 128) ? 0 : 8192) + GOFF(srow, c);

#pragma unroll
    for (int st = 0; st < 2; st++) {
#pragma unroll
        for (int c = 0; c < 4; c++) CP16(sdst[c] + st * 16384, gsrc + st * 32 + c * 8);
        CP_COMMIT();
    }

    uint32_t a_off[4][2], b_off[2][2];
#pragma unroll
    for (int i = 0; i < 4; i++) {
        const int r = wm * 64 + i * 16 + (lane & 7) + ((lane >> 3) & 1) * 8;
#pragma unroll
        for (int kt = 0; kt < 2; kt++) {
            const int c = 2 * kt + (lane >> 4);
            a_off[i][kt] = GOFF(r, c);
        }
    }
#pragma unroll
    for (int jp = 0; jp < 2; jp++) {
        const int r = wn * 32 + (2 * jp + ((lane >> 4) & 1)) * 8 + (lane & 7);
#pragma unroll
        for (int kt = 0; kt < 2; kt++) {
            const int c = 2 * kt + ((lane >> 3) & 1);
            b_off[jp][kt] = GOFF(r, c);
        }
    }

#pragma unroll 1
    for (int s = 0; s < GEMM_NSTEPS; s++) {
        if (s == GEMM_NSTEPS - 1) { CP_WAIT(0); } else { CP_WAIT(1); }
        __syncthreads();
        if (s + 2 < GEMM_NSTEPS) {
            const int st = (s + 2) % 3;
#pragma unroll
            for (int c = 0; c < 4; c++)
                CP16(sdst[c] + st * 16384, gsrc + (s + 2) * 32 + c * 8);
            CP_COMMIT();
        }

        const uint32_t ab = sb + (s % 3) * 16384;
        const uint32_t bb = ab + 8192;
#pragma unroll
        for (int kt = 0; kt < 2; kt++) {
            unsigned bf[4][2];
#pragma unroll
            for (int jp = 0; jp < 2; jp++) {
                unsigned t4[4];
                ldm_x4(t4, bb + b_off[jp][kt]);
                bf[2 * jp][0]     = t4[0]; bf[2 * jp][1]     = t4[1];
                bf[2 * jp + 1][0] = t4[2]; bf[2 * jp + 1][1] = t4[3];
            }
#pragma unroll
            for (int i = 0; i < 4; i++) {
                unsigned af[4];
                ldm_x4(af, ab + a_off[i][kt]);
#pragma unroll
                for (int j = 0; j < 4; j++) mma16(acc[i][j], af, bf[j]);
            }
        }
    }

    // ---- epilogue ----
#pragma unroll
    for (int i = 0; i < 4; i++) {
#pragma unroll
        for (int j = 0; j < 4; j++) {
            const int m = m0 + wm * 64 + i * 16 + (lane >> 2);
            const int n = n0 + wn * 32 + j * 8 + 2 * (lane & 3);
            const float2 bb2 = *(const float2*)(bias + n);
            const float bx = bb2.x * bscale, by = bb2.y * bscale;
            const float v00 = acc[i][j][0] + bx, v01 = acc[i][j][1] + by;
            const float v10 = acc[i][j][2] + bx, v11 = acc[i][j][3] + by;
            if (head_split) {
                __half* C = (__half*)Cout;
                const int hh = n >> 6, d = n & 63;
                const int b0r = m >> 11, s0r = m & (SEQ - 1);
                const int b1r = (m + 8) >> 11, s1r = (m + 8) & (SEQ - 1);
                *(unsigned*)&C[(((size_t)b0r * NUM_HEADS + hh) * SEQ + s0r) * DEPTH + d] = pack2(v00, v01);
                *(unsigned*)&C[(((size_t)b1r * NUM_HEADS + hh) * SEQ + s1r) * DEPTH + d] = pack2(v10, v11);
            } else {
                float* C = (float*)Cout;
                float2 o0; o0.x = v00; o0.y = v01;
                float2 o1; o1.x = v10; o1.y = v11;
                *(float2*)&C[(size_t)m * D_MODEL + n] = o0;
                *(float2*)&C[(size_t)(m + 8) * D_MODEL + n] = o1;
            }
        }
    }
}

__global__ __launch_bounds__(256, 2) void gemm_qkv(
    const __half* __restrict__ qf, const __half* __restrict__ kf, const __half* __restrict__ vf,
    const __half* __restrict__ wq, const float* __restrict__ bq,
    const __half* __restrict__ wk, const float* __restrict__ bk,
    const __half* __restrict__ wv, const float* __restrict__ bv,
    __half* __restrict__ qh, __half* __restrict__ kh, __half* __restrict__ vh)
{
    const int z = blockIdx.z;
    const __half* A = (z == 0) ? qf : (z == 1) ? kf : vf;
    const __half* W = (z == 0) ? wq : (z == 1) ? wk : wv;
    const float*  B = (z == 0) ? bq : (z == 1) ? bk : bv;
    __half*       C = (z == 0) ? qh : (z == 1) ? kh : vh;
    const float bs  = (z == 0) ? QSCALE : 1.0f;
    gemm_h_core(A, W, B, C, 1, blockIdx.y * 128, blockIdx.x * 128, bs);
}

__global__ __launch_bounds__(256, 2) void gemm_dense(
    const __half* __restrict__ A, const __half* __restrict__ W,
    const float* __restrict__ bias, float* __restrict__ C)
{
    gemm_h_core(A, W, bias, C, 0, blockIdx.y * 128, blockIdx.x * 128, 1.0f);
}

// ---------------------------------------------------------------------------
// fp16 FA2 causal attention, log2-domain softmax with PAIRED f16x2 ex2.
// 256 thr (8 warps), 128 q/block (16 rows/warp), 64-key tiles,
// paired q-tiles (bx, 15-bx), double-buffered cp.async K/V.
// ---------------------------------------------------------------------------
#define KOFF(r, c) ((r) * 128 + (((c) ^ ((r) & 7)) * 16))
#define ATTN_THREADS 256

__global__ __launch_bounds__(ATTN_THREADS, 2) void attn_h(
    const __half* __restrict__ Qg, const __half* __restrict__ Kg,
    const __half* __restrict__ Vg, __half* __restrict__ Og)
{
    __shared__ __align__(16) char asmm[2 * 16384];   // 2 bufs x (K 8KB + V 8KB)
    const uint32_t sb = smem_u32(asmm);

    const int tid  = threadIdx.x;
    const int lane = tid & 31;
    const int w    = tid >> 5;
    const int b    = blockIdx.z;
    const int h    = blockIdx.y;

    const size_t hoff = ((size_t)(b * NUM_HEADS + h) * SEQ) * DEPTH;
    const __half* kb = Kg + hoff;
    const __half* vb = Vg + hoff;

    const int r0 = lane >> 2;   // 0..7
    const int c0 = lane & 3;    // 0..3

    const int strow = (tid & 127) >> 1;
    const int stc0  = (tid & 1) * 4;
    const __half* stsrc = ((tid < 128) ? kb : vb) + (size_t)strow * DEPTH + stc0 * 8;
    uint32_t stdst[4];
#pragma unroll
    for (int i = 0; i < 4; i++)
        stdst[i] = sb + ((tid < 128) ? 0 : 8192) + KOFF(strow, stc0 + i);

    int rK[4];
#pragma unroll
    for (int jp = 0; jp < 4; jp++)
        rK[jp] = (2 * jp + ((lane >> 4) & 1)) * 8 + (lane & 7);
    const int hK  = (lane >> 3) & 1;
    const int rVl = (lane & 7) + ((lane >> 3) & 1) * 8;
    const int cVb = (lane >> 4) & 1;

#pragma unroll 1
    for (int pass = 0; pass < 2; pass++) {
        const int p  = pass ? (15 - (int)blockIdx.x) : (int)blockIdx.x;
        const int q0 = p * 128;

        unsigned qa[4][4];
        {
            const __half* qb = Qg + hoff + (size_t)(q0 + w * 16) * DEPTH;
#pragma unroll
            for (int kt = 0; kt < 4; kt++) {
                qa[kt][0] = *(const unsigned*)(qb + (size_t)(r0)     * DEPTH + kt * 16 + 2 * c0);
                qa[kt][1] = *(const unsigned*)(qb + (size_t)(r0 + 8) * DEPTH + kt * 16 + 2 * c0);
                qa[kt][2] = *(const unsigned*)(qb + (size_t)(r0)     * DEPTH + kt * 16 + 8 + 2 * c0);
                qa[kt][3] = *(const unsigned*)(qb + (size_t)(r0 + 8) * DEPTH + kt * 16 + 8 + 2 * c0);
            }
        }

        float o[8][4];
#pragma unroll
        for (int j = 0; j < 8; j++)
#pragma unroll
            for (int e = 0; e < 4; e++) o[j][e] = 0.f;
        float m0r = -1e30f, m1r = -1e30f;
        float l0r = 0.f,    l1r = 0.f;

        const int ntile = 2 * p + 2;
        const int qhiW  = q0 + w * 16 + 15;
        const int qrow  = q0 + w * 16 + r0;

#pragma unroll
        for (int i = 0; i < 4; i++) CP16(stdst[i], stsrc + i * 8);
        CP_COMMIT();

#pragma unroll 1
        for (int t = 0; t < ntile; t++) {
            CP_WAIT(0);
            __syncthreads();
            if (t + 1 < ntile) {
                const uint32_t bo = ((t + 1) & 1) * 16384;
                const __half* src = stsrc + (size_t)(t + 1) * 64 * DEPTH;
#pragma unroll
                for (int i = 0; i < 4; i++) CP16(stdst[i] + bo, src + i * 8);
                CP_COMMIT();
            }
            if (t * 64 > qhiW) continue;

            const uint32_t kbuf = sb + (t & 1) * 16384;
            const uint32_t vbuf = kbuf + 8192;

            // ---- S = Q @ K^T  (scores already in log2 domain) ----
            float s[8][4];
#pragma unroll
            for (int j = 0; j < 8; j++)
#pragma unroll
                for (int e = 0; e < 4; e++) s[j][e] = 0.f;
#pragma unroll
            for (int kt = 0; kt < 4; kt++) {
#pragma unroll
                for (int jp = 0; jp < 4; jp++) {
                    unsigned t4[4];
                    ldm_x4(t4, kbuf + rK[jp] * 128 + (((2 * kt + hK) ^ (rK[jp] & 7)) << 4));
                    unsigned bf0[2] = {t4[0], t4[1]};
                    unsigned bf1[2] = {t4[2], t4[3]};
                    mma16(s[2 * jp],     qa[kt], bf0);
                    mma16(s[2 * jp + 1], qa[kt], bf1);
                }
            }

            // ---- causal mask + online softmax (base-2, paired f16x2 exp) ----
            const bool diag = (t >= ntile - 2);
            float mx0 = -1e30f, mx1 = -1e30f;
#pragma unroll
            for (int j = 0; j < 8; j++) {
                if (diag) {
#pragma unroll
                    for (int e = 0; e < 4; e++) {
                        const int key = t * 64 + j * 8 + 2 * (lane & 3) + (e & 1);
                        const int qq  = qrow + ((e >> 1) << 3);
                        if (key > qq) s[j][e] = -1e30f;
                    }
                }
                mx0 = fmaxf(mx0, fmaxf(s[j][0], s[j][1]));
                mx1 = fmaxf(mx1, fmaxf(s[j][2], s[j][3]));
            }
            mx0 = fmaxf(mx0, __shfl_xor_sync(0xffffffffu, mx0, 1));
            mx0 = fmaxf(mx0, __shfl_xor_sync(0xffffffffu, mx0, 2));
            mx1 = fmaxf(mx1, __shfl_xor_sync(0xffffffffu, mx1, 1));
            mx1 = fmaxf(mx1, __shfl_xor_sync(0xffffffffu, mx1, 2));

            const float mn0 = fmaxf(m0r, mx0);
            const float mn1 = fmaxf(m1r, mx1);
            const float al0 = ex2f(m0r - mn0);
            const float al1 = ex2f(m1r - mn1);

            // p01[j] = half2(exp2(s0-mn0), exp2(s1-mn0))  -- PV A-frag material
            unsigned p01[8], p23[8];
            __half2 a01 = __floats2half2_rn(0.f, 0.f);
            __half2 a23 = a01;
#pragma unroll
            for (int j = 0; j < 8; j++) {
                p01[j] = h2ex2(pack2(s[j][0] - mn0, s[j][1] - mn0));
                p23[j] = h2ex2(pack2(s[j][2] - mn1, s[j][3] - mn1));
                a01 = __hadd2(a01, *reinterpret_cast<__half2*>(&p01[j]));
                a23 = __hadd2(a23, *reinterpret_cast<__half2*>(&p23[j]));
            }
            float ls0 = __low2float(a01) + __high2float(a01);
            float ls1 = __low2float(a23) + __high2float(a23);
            ls0 += __shfl_xor_sync(0xffffffffu, ls0, 1);
            ls0 += __shfl_xor_sync(0xffffffffu, ls0, 2);
            ls1 += __shfl_xor_sync(0xffffffffu, ls1, 1);
            ls1 += __shfl_xor_sync(0xffffffffu, ls1, 2);

            l0r = l0r * al0 + ls0;
            l1r = l1r * al1 + ls1;
            m0r = mn0; m1r = mn1;

#pragma unroll
            for (int j = 0; j < 8; j++) {
                o[j][0] *= al0; o[j][1] *= al0;
                o[j][2] *= al1; o[j][3] *= al1;
            }

            // ---- O += P @ V : A-frags are the h2ex2 outputs directly ----
#pragma unroll
            for (int kt = 0; kt < 4; kt++) {
                unsigned af[4];
                af[0] = p01[2 * kt];
                af[1] = p23[2 * kt];
                af[2] = p01[2 * kt + 1];
                af[3] = p23[2 * kt + 1];
                const int rV = kt * 16 + rVl;
#pragma unroll
                for (int jp = 0; jp < 4; jp++) {
                    unsigned t4[4];
                    ldm_x4_t(t4, vbuf + rV * 128 + (((2 * jp + cVb) ^ (rV & 7)) << 4));
                    unsigned bf0[2] = {t4[0], t4[1]};
                    unsigned bf1[2] = {t4[2], t4[3]};
                    mma16(o[2 * jp],     af, bf0);
                    mma16(o[2 * jp + 1], af, bf1);
                }
            }
        }

        // ---- epilogue ----
        const float inv0 = 1.f / l0r;
        const float inv1 = 1.f / l1r;
        const int qq = q0 + w * 16 + r0;
#pragma unroll
        for (int j = 0; j < 8; j++) {
            const int col = j * 8 + 2 * (lane & 3);
            *(unsigned*)&Og[((size_t)(b * SEQ + qq))     * D_MODEL + h * DEPTH + col]
                = pack2(o[j][0] * inv0, o[j][1] * inv0);
            *(unsigned*)&Og[((size_t)(b * SEQ + qq + 8)) * D_MODEL + h * DEPTH + col]
                = pack2(o[j][2] * inv1, o[j][3] * inv1);
        }
        __syncthreads();   // buffers reused from t=0 next pass
    }
}

// ---------------------------------------------------------------------------
// Launch
// ---------------------------------------------------------------------------
extern "C" void kernel_launch(void* const* d_in, const int* in_sizes, int n_in,
                              void* d_out, int out_size)
{
    const float* v       = (const float*)d_in[0];
    const float* k       = (const float*)d_in[1];
    const float* q       = (const float*)d_in[2];
    // d_in[3] = mask (causal triu) -- analytic in attn kernel
    const float* wq_w    = (const float*)d_in[4];
    const float* wq_b    = (const float*)d_in[5];
    const float* wk_w    = (const float*)d_in[6];
    const float* wk_b    = (const float*)d_in[7];
    const float* wv_w    = (const float*)d_in[8];
    const float* wv_b    = (const float*)d_in[9];
    const float* dense_w = (const float*)d_in[10];
    const float* dense_b = (const float*)d_in[11];
    float* out = (float*)d_out;

    __half *qf, *kf, *vf, *wq, *wk, *wv, *wd, *qh, *kh, *vh, *att;
    cudaGetSymbolAddress((void**)&qf,  g_qf);
    cudaGetSymbolAddress((void**)&kf,  g_kf);
    cudaGetSymbolAddress((void**)&vf,  g_vf);
    cudaGetSymbolAddress((void**)&wq,  g_wq);
    cudaGetSymbolAddress((void**)&wk,  g_wk);
    cudaGetSymbolAddress((void**)&wv,  g_wv);
    cudaGetSymbolAddress((void**)&wd,  g_wd);
    cudaGetSymbolAddress((void**)&qh,  g_qh);
    cudaGetSymbolAddress((void**)&kh,  g_kh);
    cudaGetSymbolAddress((void**)&vh,  g_vh);
    cudaGetSymbolAddress((void**)&att, g_att);

    // 1) f32 -> f16 conversions (single launch; wq pre-scaled by QSCALE)
    cvt_all<<<dim3(M_ROWS * D_MODEL / 4 / 256, 1, 7), 256>>>(
        q, k, v, wq_w, wk_w, wv_w, dense_w,
        qf, kf, vf, wq, wk, wv, wd);

    // 2) Q/K/V projections (head-split half output)
    const dim3 pgrid(D_MODEL / 128, M_ROWS / 128, 3);   // (8, 32, 3)
    gemm_qkv<<<pgrid, 256>>>(qf, kf, vf, wq, wq_b, wk, wk_b, wv, wv_b, qh, kh, vh);

    // 3) attention (half in, half out)
    const dim3 agrid(SEQ / 256, NUM_HEADS, BATCH);      // (8, 16, 2) paired tiles
    attn_h<<<agrid, ATTN_THREADS>>>(qh, kh, vh, att);

    // 4) dense (half in, f32 out)
    const dim3 dgrid(D_MODEL / 128, M_ROWS / 128);      // (8, 32)
    gemm_dense<<<dgrid, 256>>>(att, wd, dense_b, out);
}

// round 13
// speedup vs baseline: 2.3009x; 1.0459x over previous
#include <cuda_runtime.h>
#include <cuda_fp16.h>
#include <cstddef>
#include <cstdint>

#define D_MODEL   1024
#define NUM_HEADS 16
#define DEPTH     64
#define BATCH     2
#define SEQ       2048
#define M_ROWS    (BATCH * SEQ)   // 4096

// Q-path scale: (1/sqrt(64)) * log2(e)  — folds softmax scaling + exp->ex2
#define QSCALE 0.18033688011112042f

// ---------------------------------------------------------------------------
// Scratch (all fp16 intermediates; f32 only for biases & final output)
// ---------------------------------------------------------------------------
__device__ __half g_qf[M_ROWS * D_MODEL];    // converted inputs
__device__ __half g_kf[M_ROWS * D_MODEL];
__device__ __half g_vf[M_ROWS * D_MODEL];
__device__ __half g_wq[D_MODEL * D_MODEL];   // converted weights (wq pre-scaled)
__device__ __half g_wk[D_MODEL * D_MODEL];
__device__ __half g_wv[D_MODEL * D_MODEL];
__device__ __half g_wd[D_MODEL * D_MODEL];
__device__ __half g_qh[BATCH * NUM_HEADS * SEQ * DEPTH];   // projections [B,H,S,64]
__device__ __half g_kh[BATCH * NUM_HEADS * SEQ * DEPTH];
__device__ __half g_vh[BATCH * NUM_HEADS * SEQ * DEPTH];
__device__ __half g_att[M_ROWS * D_MODEL];   // attention out, concat layout

// ---------------------------------------------------------------------------
// Helpers
// ---------------------------------------------------------------------------
__device__ __forceinline__ uint32_t smem_u32(const void* p) {
    uint32_t a;
    asm("{ .reg .u64 t; cvta.to.shared.u64 t, %1; cvt.u32.u64 %0, t; }" : "=r"(a) : "l"(p));
    return a;
}

__device__ __forceinline__ unsigned pack2(float a, float b) {
    __half2 h = __floats2half2_rn(a, b);   // low half = a
    return *reinterpret_cast<unsigned*>(&h);
}

__device__ __forceinline__ float ex2f(float x) {
    float y;
    asm("ex2.approx.f32 %0, %1;" : "=f"(y) : "f"(x));
    return y;
}

// paired exponential: ex2 on both halves of a packed half2
__device__ __forceinline__ unsigned h2ex2(unsigned x) {
    unsigned y;
    asm("ex2.approx.f16x2 %0, %1;" : "=r"(y) : "r"(x));
    return y;
}

__device__ __forceinline__ void mma16(float* c, const unsigned* a, const unsigned* b) {
    asm volatile(
        "mma.sync.aligned.m16n8k16.row.col.f32.f16.f16.f32 "
        "{%0,%1,%2,%3},{%4,%5,%6,%7},{%8,%9},{%0,%1,%2,%3};"
        : "+f"(c[0]), "+f"(c[1]), "+f"(c[2]), "+f"(c[3])
        : "r"(a[0]), "r"(a[1]), "r"(a[2]), "r"(a[3]), "r"(b[0]), "r"(b[1]));
}

__device__ __forceinline__ void ldm_x4(unsigned* d, uint32_t addr) {
    asm volatile("ldmatrix.sync.aligned.m8n8.x4.shared.b16 {%0,%1,%2,%3}, [%4];"
                 : "=r"(d[0]), "=r"(d[1]), "=r"(d[2]), "=r"(d[3]) : "r"(addr));
}
__device__ __forceinline__ void ldm_x4_t(unsigned* d, uint32_t addr) {
    asm volatile("ldmatrix.sync.aligned.m8n8.x4.trans.shared.b16 {%0,%1,%2,%3}, [%4];"
                 : "=r"(d[0]), "=r"(d[1]), "=r"(d[2]), "=r"(d[3]) : "r"(addr));
}

#define CP16(dst, src) \
    asm volatile("cp.async.cg.shared.global [%0], [%1], 16;" :: "r"(dst), "l"(src) : "memory")
#define CP_COMMIT() asm volatile("cp.async.commit_group;" ::: "memory")
#define CP_WAIT(n)  asm volatile("cp.async.wait_group %0;" :: "n"(n) : "memory")

// ---------------------------------------------------------------------------
// Conversion kernel (f32 -> f16): z 0..2 inputs (q,k,v), 3..6 weights.
// wq (z==3) pre-scaled by QSCALE.
// ---------------------------------------------------------------------------
__global__ void cvt_all(const float* __restrict__ q, const float* __restrict__ k,
                        const float* __restrict__ v,
                        const float* __restrict__ w0, const float* __restrict__ w1,
                        const float* __restrict__ w2, const float* __restrict__ w3,
                        __half* dq, __half* dk, __half* dv,
                        __half* d0, __half* d1, __half* d2, __half* d3)
{
    const int z = blockIdx.z;
    const int n = (z < 3) ? (M_ROWS * D_MODEL / 4) : (D_MODEL * D_MODEL / 4);
    const int i = blockIdx.x * blockDim.x + threadIdx.x;
    if (i >= n) return;
    const float* s;
    __half* d;
    float sc = 1.0f;
    switch (z) {
        case 0: s = q;  d = dq; break;
        case 1: s = k;  d = dk; break;
        case 2: s = v;  d = dv; break;
        case 3: s = w0; d = d0; sc = QSCALE; break;
        case 4: s = w1; d = d1; break;
        case 5: s = w2; d = d2; break;
        default: s = w3; d = d3; break;
    }
    const float4 f = ((const float4*)s)[i];
    uint2 u;
    u.x = pack2(f.x * sc, f.y * sc);
    u.y = pack2(f.z * sc, f.w * sc);
    ((uint2*)d)[i] = u;
}

// ---------------------------------------------------------------------------
// fp16 GEMM: C = A(M,K) @ W^T(N,K) + bias*bscale.  Block 128x128, BK=32,
// 256 thr, 8 warps (2m x 4n), warp tile 64x32, 5-stage cp.async pipeline
// (dynamic smem 80KB; wait_group 3 keeps 4 fetches in flight).
//   GOFF(r,c) = (r>>1)*128 + ((((r&1)*4 + c) ^ ((r>>1)&7)) * 16)   [bytes]
// ---------------------------------------------------------------------------
#define GOFF(r, c) ((((r) >> 1) * 128) + ((((((r) & 1) * 4) + (c)) ^ (((r) >> 1) & 7)) * 16))
#define GEMM_NSTEPS 32   // 1024 / 32
#define GEMM_NSTAGE 5
#define GEMM_STAGE_BYTES 16384
#define GEMM_SMEM_BYTES (GEMM_NSTAGE * GEMM_STAGE_BYTES)   // 81920

__device__ __forceinline__ void gemm_h_core(
    const __half* __restrict__ A, const __half* __restrict__ W,
    const float* __restrict__ bias, void* __restrict__ Cout,
    int head_split, int m0, int n0, float bscale)
{
    extern __shared__ __align__(16) char gsm[];
    const uint32_t sb = smem_u32(gsm);

    const int tid  = threadIdx.x;
    const int lane = tid & 31;
    const int w    = tid >> 5;
    const int wm   = w >> 2;           // 0..1
    const int wn   = w & 3;            // 0..3

    float acc[4][4][4];
#pragma unroll
    for (int i = 0; i < 4; i++)
#pragma unroll
        for (int j = 0; j < 4; j++)
#pragma unroll
            for (int e = 0; e < 4; e++) acc[i][j][e] = 0.f;

    const int srow = tid & 127;
    const __half* gsrc = (tid < 128) ? (A + (size_t)(m0 + srow) * D_MODEL)
                                     : (W + (size_t)(n0 + srow) * D_MODEL);
    uint32_t sdst[4];
#pragma unroll
    for (int c = 0; c < 4; c++)
        sdst[c] = sb + ((tid < 128) ? 0 : 8192) + GOFF(srow, c);

    // prologue: stages 0..3 (4 groups in flight)
#pragma unroll
    for (int st = 0; st < 4; st++) {
#pragma unroll
        for (int c = 0; c < 4; c++)
            CP16(sdst[c] + st * GEMM_STAGE_BYTES, gsrc + st * 32 + c * 8);
        CP_COMMIT();
    }

    uint32_t a_off[4][2], b_off[2][2];
#pragma unroll
    for (int i = 0; i < 4; i++) {
        const int r = wm * 64 + i * 16 + (lane & 7) + ((lane >> 3) & 1) * 8;
#pragma unroll
        for (int kt = 0; kt < 2; kt++) {
            const int c = 2 * kt + (lane >> 4);
            a_off[i][kt] = GOFF(r, c);
        }
    }
#pragma unroll
    for (int jp = 0; jp < 2; jp++) {
        const int r = wn * 32 + (2 * jp + ((lane >> 4) & 1)) * 8 + (lane & 7);
#pragma unroll
        for (int kt = 0; kt < 2; kt++) {
            const int c = 2 * kt + ((lane >> 3) & 1);
            b_off[jp][kt] = GOFF(r, c);
        }
    }

#pragma unroll 1
    for (int s = 0; s < GEMM_NSTEPS; s++) {
        CP_WAIT(3);            // group s retired (one group committed per iter)
        __syncthreads();
        if (s + 4 < GEMM_NSTEPS) {
            const int st = (s + 4) % GEMM_NSTAGE;
#pragma unroll
            for (int c = 0; c < 4; c++)
                CP16(sdst[c] + st * GEMM_STAGE_BYTES, gsrc + (s + 4) * 32 + c * 8);
        }
        CP_COMMIT();           // always one group per iteration (may be empty)

        const uint32_t ab = sb + (s % GEMM_NSTAGE) * GEMM_STAGE_BYTES;
        const uint32_t bb = ab + 8192;
#pragma unroll
        for (int kt = 0; kt < 2; kt++) {
            unsigned bf[4][2];
#pragma unroll
            for (int jp = 0; jp < 2; jp++) {
                unsigned t4[4];
                ldm_x4(t4, bb + b_off[jp][kt]);
                bf[2 * jp][0]     = t4[0]; bf[2 * jp][1]     = t4[1];
                bf[2 * jp + 1][0] = t4[2]; bf[2 * jp + 1][1] = t4[3];
            }
#pragma unroll
            for (int i = 0; i < 4; i++) {
                unsigned af[4];
                ldm_x4(af, ab + a_off[i][kt]);
#pragma unroll
                for (int j = 0; j < 4; j++) mma16(acc[i][j], af, bf[j]);
            }
        }
    }

    // ---- epilogue ----
#pragma unroll
    for (int i = 0; i < 4; i++) {
#pragma unroll
        for (int j = 0; j < 4; j++) {
            const int m = m0 + wm * 64 + i * 16 + (lane >> 2);
            const int n = n0 + wn * 32 + j * 8 + 2 * (lane & 3);
            const float2 bb2 = *(const float2*)(bias + n);
            const float bx = bb2.x * bscale, by = bb2.y * bscale;
            const float v00 = acc[i][j][0] + bx, v01 = acc[i][j][1] + by;
            const float v10 = acc[i][j][2] + bx, v11 = acc[i][j][3] + by;
            if (head_split) {
                __half* C = (__half*)Cout;
                const int hh = n >> 6, d = n & 63;
                const int b0r = m >> 11, s0r = m & (SEQ - 1);
                const int b1r = (m + 8) >> 11, s1r = (m + 8) & (SEQ - 1);
                *(unsigned*)&C[(((size_t)b0r * NUM_HEADS + hh) * SEQ + s0r) * DEPTH + d] = pack2(v00, v01);
                *(unsigned*)&C[(((size_t)b1r * NUM_HEADS + hh) * SEQ + s1r) * DEPTH + d] = pack2(v10, v11);
            } else {
                float* C = (float*)Cout;
                float2 o0; o0.x = v00; o0.y = v01;
                float2 o1; o1.x = v10; o1.y = v11;
                *(float2*)&C[(size_t)m * D_MODEL + n] = o0;
                *(float2*)&C[(size_t)(m + 8) * D_MODEL + n] = o1;
            }
        }
    }
}

__global__ __launch_bounds__(256, 2) void gemm_qkv(
    const __half* __restrict__ qf, const __half* __restrict__ kf, const __half* __restrict__ vf,
    const __half* __restrict__ wq, const float* __restrict__ bq,
    const __half* __restrict__ wk, const float* __restrict__ bk,
    const __half* __restrict__ wv, const float* __restrict__ bv,
    __half* __restrict__ qh, __half* __restrict__ kh, __half* __restrict__ vh)
{
    const int z = blockIdx.z;
    const __half* A = (z == 0) ? qf : (z == 1) ? kf : vf;
    const __half* W = (z == 0) ? wq : (z == 1) ? wk : wv;
    const float*  B = (z == 0) ? bq : (z == 1) ? bk : bv;
    __half*       C = (z == 0) ? qh : (z == 1) ? kh : vh;
    const float bs  = (z == 0) ? QSCALE : 1.0f;
    gemm_h_core(A, W, B, C, 1, blockIdx.y * 128, blockIdx.x * 128, bs);
}

__global__ __launch_bounds__(256, 2) void gemm_dense(
    const __half* __restrict__ A, const __half* __restrict__ W,
    const float* __restrict__ bias, float* __restrict__ C)
{
    gemm_h_core(A, W, bias, C, 0, blockIdx.y * 128, blockIdx.x * 128, 1.0f);
}

// ---------------------------------------------------------------------------
// fp16 FA2 causal attention, log2-domain softmax with PAIRED f16x2 ex2.
// 256 thr (8 warps), 128 q/block (16 rows/warp), 64-key tiles,
// paired q-tiles (bx, 15-bx), double-buffered cp.async K/V.
// ---------------------------------------------------------------------------
#define KOFF(r, c) ((r) * 128 + (((c) ^ ((r) & 7)) * 16))
#define ATTN_THREADS 256

__global__ __launch_bounds__(ATTN_THREADS, 2) void attn_h(
    const __half* __restrict__ Qg, const __half* __restrict__ Kg,
    const __half* __restrict__ Vg, __half* __restrict__ Og)
{
    __shared__ __align__(16) char asmm[2 * 16384];   // 2 bufs x (K 8KB + V 8KB)
    const uint32_t sb = smem_u32(asmm);

    const int tid  = threadIdx.x;
    const int lane = tid & 31;
    const int w    = tid >> 5;
    const int b    = blockIdx.z;
    const int h    = blockIdx.y;

    const size_t hoff = ((size_t)(b * NUM_HEADS + h) * SEQ) * DEPTH;
    const __half* kb = Kg + hoff;
    const __half* vb = Vg + hoff;

    const int r0 = lane >> 2;   // 0..7
    const int c0 = lane & 3;    // 0..3

    const int strow = (tid & 127) >> 1;
    const int stc0  = (tid & 1) * 4;
    const __half* stsrc = ((tid < 128) ? kb : vb) + (size_t)strow * DEPTH + stc0 * 8;
    uint32_t stdst[4];
#pragma unroll
    for (int i = 0; i < 4; i++)
        stdst[i] = sb + ((tid < 128) ? 0 : 8192) + KOFF(strow, stc0 + i);

    int rK[4];
#pragma unroll
    for (int jp = 0; jp < 4; jp++)
        rK[jp] = (2 * jp + ((lane >> 4) & 1)) * 8 + (lane & 7);
    const int hK  = (lane >> 3) & 1;
    const int rVl = (lane & 7) + ((lane >> 3) & 1) * 8;
    const int cVb = (lane >> 4) & 1;

#pragma unroll 1
    for (int pass = 0; pass < 2; pass++) {
        const int p  = pass ? (15 - (int)blockIdx.x) : (int)blockIdx.x;
        const int q0 = p * 128;

        unsigned qa[4][4];
        {
            const __half* qb = Qg + hoff + (size_t)(q0 + w * 16) * DEPTH;
#pragma unroll
            for (int kt = 0; kt < 4; kt++) {
                qa[kt][0] = *(const unsigned*)(qb + (size_t)(r0)     * DEPTH + kt * 16 + 2 * c0);
                qa[kt][1] = *(const unsigned*)(qb + (size_t)(r0 + 8) * DEPTH + kt * 16 + 2 * c0);
                qa[kt][2] = *(const unsigned*)(qb + (size_t)(r0)     * DEPTH + kt * 16 + 8 + 2 * c0);
                qa[kt][3] = *(const unsigned*)(qb + (size_t)(r0 + 8) * DEPTH + kt * 16 + 8 + 2 * c0);
            }
        }

        float o[8][4];
#pragma unroll
        for (int j = 0; j < 8; j++)
#pragma unroll
            for (int e = 0; e < 4; e++) o[j][e] = 0.f;
        float m0r = -1e30f, m1r = -1e30f;
        float l0r = 0.f,    l1r = 0.f;

        const int ntile = 2 * p + 2;
        const int qhiW  = q0 + w * 16 + 15;
        const int qrow  = q0 + w * 16 + r0;

#pragma unroll
        for (int i = 0; i < 4; i++) CP16(stdst[i], stsrc + i * 8);
        CP_COMMIT();

#pragma unroll 1
        for (int t = 0; t < ntile; t++) {
            CP_WAIT(0);
            __syncthreads();
            if (t + 1 < ntile) {
                const uint32_t bo = ((t + 1) & 1) * 16384;
                const __half* src = stsrc + (size_t)(t + 1) * 64 * DEPTH;
#pragma unroll
                for (int i = 0; i < 4; i++) CP16(stdst[i] + bo, src + i * 8);
                CP_COMMIT();
            }
            if (t * 64 > qhiW) continue;

            const uint32_t kbuf = sb + (t & 1) * 16384;
            const uint32_t vbuf = kbuf + 8192;

            // ---- S = Q @ K^T  (scores already in log2 domain) ----
            float s[8][4];
#pragma unroll
            for (int j = 0; j < 8; j++)
#pragma unroll
                for (int e = 0; e < 4; e++) s[j][e] = 0.f;
#pragma unroll
            for (int kt = 0; kt < 4; kt++) {
#pragma unroll
                for (int jp = 0; jp < 4; jp++) {
                    unsigned t4[4];
                    ldm_x4(t4, kbuf + rK[jp] * 128 + (((2 * kt + hK) ^ (rK[jp] & 7)) << 4));
                    unsigned bf0[2] = {t4[0], t4[1]};
                    unsigned bf1[2] = {t4[2], t4[3]};
                    mma16(s[2 * jp],     qa[kt], bf0);
                    mma16(s[2 * jp + 1], qa[kt], bf1);
                }
            }

            // ---- causal mask + online softmax (base-2, paired f16x2 exp) ----
            const bool diag = (t >= ntile - 2);
            float mx0 = -1e30f, mx1 = -1e30f;
#pragma unroll
            for (int j = 0; j < 8; j++) {
                if (diag) {
#pragma unroll
                    for (int e = 0; e < 4; e++) {
                        const int key = t * 64 + j * 8 + 2 * (lane & 3) + (e & 1);
                        const int qq  = qrow + ((e >> 1) << 3);
                        if (key > qq) s[j][e] = -1e30f;
                    }
                }
                mx0 = fmaxf(mx0, fmaxf(s[j][0], s[j][1]));
                mx1 = fmaxf(mx1, fmaxf(s[j][2], s[j][3]));
            }
            mx0 = fmaxf(mx0, __shfl_xor_sync(0xffffffffu, mx0, 1));
            mx0 = fmaxf(mx0, __shfl_xor_sync(0xffffffffu, mx0, 2));
            mx1 = fmaxf(mx1, __shfl_xor_sync(0xffffffffu, mx1, 1));
            mx1 = fmaxf(mx1, __shfl_xor_sync(0xffffffffu, mx1, 2));

            const float mn0 = fmaxf(m0r, mx0);
            const float mn1 = fmaxf(m1r, mx1);
            const float al0 = ex2f(m0r - mn0);
            const float al1 = ex2f(m1r - mn1);

            unsigned p01[8], p23[8];
            __half2 a01 = __floats2half2_rn(0.f, 0.f);
            __half2 a23 = a01;
#pragma unroll
            for (int j = 0; j < 8; j++) {
                p01[j] = h2ex2(pack2(s[j][0] - mn0, s[j][1] - mn0));
                p23[j] = h2ex2(pack2(s[j][2] - mn1, s[j][3] - mn1));
                a01 = __hadd2(a01, *reinterpret_cast<__half2*>(&p01[j]));
                a23 = __hadd2(a23, *reinterpret_cast<__half2*>(&p23[j]));
            }
            float ls0 = __low2float(a01) + __high2float(a01);
            float ls1 = __low2float(a23) + __high2float(a23);
            ls0 += __shfl_xor_sync(0xffffffffu, ls0, 1);
            ls0 += __shfl_xor_sync(0xffffffffu, ls0, 2);
            ls1 += __shfl_xor_sync(0xffffffffu, ls1, 1);
            ls1 += __shfl_xor_sync(0xffffffffu, ls1, 2);

            l0r = l0r * al0 + ls0;
            l1r = l1r * al1 + ls1;
            m0r = mn0; m1r = mn1;

#pragma unroll
            for (int j = 0; j < 8; j++) {
                o[j][0] *= al0; o[j][1] *= al0;
                o[j][2] *= al1; o[j][3] *= al1;
            }

            // ---- O += P @ V : A-frags are the h2ex2 outputs directly ----
#pragma unroll
            for (int kt = 0; kt < 4; kt++) {
                unsigned af[4];
                af[0] = p01[2 * kt];
                af[1] = p23[2 * kt];
                af[2] = p01[2 * kt + 1];
                af[3] = p23[2 * kt + 1];
                const int rV = kt * 16 + rVl;
#pragma unroll
                for (int jp = 0; jp < 4; jp++) {
                    unsigned t4[4];
                    ldm_x4_t(t4, vbuf + rV * 128 + (((2 * jp + cVb) ^ (rV & 7)) << 4));
                    unsigned bf0[2] = {t4[0], t4[1]};
                    unsigned bf1[2] = {t4[2], t4[3]};
                    mma16(o[2 * jp],     af, bf0);
                    mma16(o[2 * jp + 1], af, bf1);
                }
            }
        }

        // ---- epilogue ----
        const float inv0 = 1.f / l0r;
        const float inv1 = 1.f / l1r;
        const int qq = q0 + w * 16 + r0;
#pragma unroll
        for (int j = 0; j < 8; j++) {
            const int col = j * 8 + 2 * (lane & 3);
            *(unsigned*)&Og[((size_t)(b * SEQ + qq))     * D_MODEL + h * DEPTH + col]
                = pack2(o[j][0] * inv0, o[j][1] * inv0);
            *(unsigned*)&Og[((size_t)(b * SEQ + qq + 8)) * D_MODEL + h * DEPTH + col]
                = pack2(o[j][2] * inv1, o[j][3] * inv1);
        }
        __syncthreads();   // buffers reused from t=0 next pass
    }
}

// ---------------------------------------------------------------------------
// Launch
// ---------------------------------------------------------------------------
extern "C" void kernel_launch(void* const* d_in, const int* in_sizes, int n_in,
                              void* d_out, int out_size)
{
    const float* v       = (const float*)d_in[0];
    const float* k       = (const float*)d_in[1];
    const float* q       = (const float*)d_in[2];
    // d_in[3] = mask (causal triu) -- analytic in attn kernel
    const float* wq_w    = (const float*)d_in[4];
    const float* wq_b    = (const float*)d_in[5];
    const float* wk_w    = (const float*)d_in[6];
    const float* wk_b    = (const float*)d_in[7];
    const float* wv_w    = (const float*)d_in[8];
    const float* wv_b    = (const float*)d_in[9];
    const float* dense_w = (const float*)d_in[10];
    const float* dense_b = (const float*)d_in[11];
    float* out = (float*)d_out;

    __half *qf, *kf, *vf, *wq, *wk, *wv, *wd, *qh, *kh, *vh, *att;
    cudaGetSymbolAddress((void**)&qf,  g_qf);
    cudaGetSymbolAddress((void**)&kf,  g_kf);
    cudaGetSymbolAddress((void**)&vf,  g_vf);
    cudaGetSymbolAddress((void**)&wq,  g_wq);
    cudaGetSymbolAddress((void**)&wk,  g_wk);
    cudaGetSymbolAddress((void**)&wv,  g_wv);
    cudaGetSymbolAddress((void**)&wd,  g_wd);
    cudaGetSymbolAddress((void**)&qh,  g_qh);
    cudaGetSymbolAddress((void**)&kh,  g_kh);
    cudaGetSymbolAddress((void**)&vh,  g_vh);
    cudaGetSymbolAddress((void**)&att, g_att);

    cudaFuncSetAttribute(gemm_qkv,
                         cudaFuncAttributeMaxDynamicSharedMemorySize, GEMM_SMEM_BYTES);
    cudaFuncSetAttribute(gemm_dense,
                         cudaFuncAttributeMaxDynamicSharedMemorySize, GEMM_SMEM_BYTES);

    // 1) f32 -> f16 conversions (single launch; wq pre-scaled by QSCALE)
    cvt_all<<<dim3(M_ROWS * D_MODEL / 4 / 256, 1, 7), 256>>>(
        q, k, v, wq_w, wk_w, wv_w, dense_w,
        qf, kf, vf, wq, wk, wv, wd);

    // 2) Q/K/V projections (head-split half output)
    const dim3 pgrid(D_MODEL / 128, M_ROWS / 128, 3);   // (8, 32, 3)
    gemm_qkv<<<pgrid, 256, GEMM_SMEM_BYTES>>>(qf, kf, vf, wq, wq_b, wk, wk_b,
                                              wv, wv_b, qh, kh, vh);

    // 3) attention (half in, half out)
    const dim3 agrid(SEQ / 256, NUM_HEADS, BATCH);      // (8, 16, 2) paired tiles
    attn_h<<<agrid, ATTN_THREADS>>>(qh, kh, vh, att);

    // 4) dense (half in, f32 out)
    const dim3 dgrid(D_MODEL / 128, M_ROWS / 128);      // (8, 32)
    gemm_dense<<<dgrid, 256, GEMM_SMEM_BYTES>>>(att, wd, dense_b, out);
}